// round 10
// baseline (speedup 1.0000x reference)
#include <cuda_runtime.h>
#include <cuda_bf16.h>
#include <cstdint>
#include <math.h>

// LSTM B=64, T=512, I=256, H=1024, O=1 — persistent mma.sync kernel.
// W resident in smem (swizzled, 160KB); B (act) via 4-deep swizzled cp.async ring.
// gates[4096,64] = W_ext[4096,1280] @ act[1280,64]; 128 CTAs x M=32 rows.
// bf16 hi/lo split both operands, 3-term MMA, fp32 accum.
// All 8 warps active every chunk: m0=(w&1)*16, n0=(w>>1)*16.

#define NCTA 128
#define TPB  256
#define Tsz  512
#define Bsz  64
#define Isz  256
#define Hsz  1024
#define NCHK 20
#define ACH   8192                      // per-chunk A bytes (hi 4096 + lo 4096)
#define AHALF 4096
#define ABYTES (NCHK * ACH)             // 163840 — W resident
#define BBUF  16384                     // per B buffer (hi 8192 + lo 8192)
#define BLHALF 8192
#define BOFF  ABYTES
#define SMEM_DYN (ABYTES + 4 * BBUF)    // 229376
#define EXST 66

// ---------------- static device scratch ----------------
__device__ __align__(16) __nv_bfloat16 g_WrH[NCTA * 32 * 1280];
__device__ __align__(16) __nv_bfloat16 g_WrL[NCTA * 32 * 1280];
__device__ __align__(16) __nv_bfloat16 g_xh[(size_t)Bsz * Tsz * Isz];
__device__ __align__(16) __nv_bfloat16 g_xl[(size_t)Bsz * Tsz * Isz];
__device__ __align__(16) __nv_bfloat16 g_hh[2][Bsz * Hsz];
__device__ __align__(16) __nv_bfloat16 g_hl[2][Bsz * Hsz];
__device__ float    g_hf[Bsz * Hsz];
__device__ float    g_bsum[NCTA * 32];
__device__ unsigned g_cnt;

// ---------------- PTX helpers ----------------
__device__ __forceinline__ uint32_t smem_u32(const void* p) {
    uint32_t a;
    asm("{ .reg .u64 t; cvta.to.shared.u64 t, %1; cvt.u32.u64 %0, t; }" : "=r"(a) : "l"(p));
    return a;
}
__device__ __forceinline__ void cp16(uint32_t dst, const void* src) {
    asm volatile("cp.async.cg.shared.global [%0], [%1], 16;" :: "r"(dst), "l"(src));
}
#define CP_COMMIT() asm volatile("cp.async.commit_group;")
#define CP_WAIT(n)  asm volatile("cp.async.wait_group %0;" :: "n"(n) : "memory")

__device__ __forceinline__ void ldsm4(uint32_t* r, uint32_t a) {
    asm volatile("ldmatrix.sync.aligned.m8n8.x4.shared.b16 {%0,%1,%2,%3}, [%4];"
                 : "=r"(r[0]), "=r"(r[1]), "=r"(r[2]), "=r"(r[3]) : "r"(a));
}
__device__ __forceinline__ void mma16816(float* c, const uint32_t* a,
                                         uint32_t b0, uint32_t b1) {
    asm volatile(
        "mma.sync.aligned.m16n8k16.row.col.f32.bf16.bf16.f32 "
        "{%0,%1,%2,%3}, {%4,%5,%6,%7}, {%8,%9}, {%0,%1,%2,%3};"
        : "+f"(c[0]), "+f"(c[1]), "+f"(c[2]), "+f"(c[3])
        : "r"(a[0]), "r"(a[1]), "r"(a[2]), "r"(a[3]), "r"(b0), "r"(b1));
}

__device__ __forceinline__ float sigmoidf_(float v) { return 1.0f / (1.0f + expf(-v)); }

// ---------------- staging: one B K-chunk (act hi/lo), swizzled ----------------
__device__ __forceinline__ void stage_b(int tid, int t, int c, uint32_t buf) {
    #pragma unroll
    for (int i = 0; i < 2; i++) {
        int idx = tid + i * TPB;            // 0..511
        int b = idx >> 3, q = idx & 7;
        uint32_t d = (uint32_t)(b * 128 + ((q * 16) ^ ((b & 7) << 4)));
        const __nv_bfloat16 *sh, *sl;
        if (c < 4) {
            size_t o = ((size_t)b * Tsz + t) * Isz + c * 64 + q * 8;
            sh = g_xh + o; sl = g_xl + o;
        } else {
            size_t o = (size_t)b * Hsz + (c - 4) * 64 + q * 8;
            sh = g_hh[t & 1] + o; sl = g_hl[t & 1] + o;
        }
        cp16(buf + d, sh);
        cp16(buf + BLHALF + d, sl);
    }
}

// ---------------- persistent LSTM kernel (final FC folded in) ----------------
__global__ void __launch_bounds__(TPB, 1)
lstm_persist(const float* __restrict__ fcW, const float* __restrict__ fcb,
             float* __restrict__ out)
{
    extern __shared__ __align__(16) char sm[];
    const uint32_t smu = smem_u32(sm);
    float* exch = (float*)(sm + BOFF);       // aliases B ring (safe by sync order)

    const int tid = threadIdx.x;
    const int cta = blockIdx.x;
    const int w = tid >> 5, lane = tid & 31;
    const int m0 = (w & 1) * 16;
    const int n0 = (w >> 1) * 16;            // 0,16,32,48

    // ldsm lane constants (swizzled): addr = tile + row*128 + ((ks*32+sel)^xrow)
    const int aRow = m0 + (lane & 15);
    const uint32_t aRB  = (uint32_t)(aRow * 128);
    const uint32_t aX   = (uint32_t)((aRow & 7) << 4);
    const uint32_t aSel = (lane & 16) ? 16u : 0u;
    const int bRow = n0 + (lane & 7) + ((lane & 16) ? 8 : 0);
    const uint32_t bRB  = (uint32_t)(bRow * 128);
    const uint32_t bX   = (uint32_t)((bRow & 7) << 4);
    const uint32_t bSel = (lane & 8) ? 16u : 0u;

    // epilogue frag mapping
    const int er = m0 + (lane >> 2);
    const int ecol = 2 * (lane & 3);

    // pointwise mapping: 2 cells (pb, pj0..pj0+1)
    const int pb = tid & 63;
    const int pj0 = (tid >> 6) * 2;
    float bias_pw[2][4];
    #pragma unroll
    for (int i = 0; i < 2; i++)
        #pragma unroll
        for (int g = 0; g < 4; g++)
            bias_pw[i][g] = g_bsum[cta * 32 + g * 8 + pj0 + i];
    float c_reg[2] = {0.0f, 0.0f};

    // ---- stage resident W once (swizzled): 10240 cp16 ----
    {
        const __nv_bfloat16* wh = g_WrH + (size_t)cta * 32 * 1280;
        const __nv_bfloat16* wl = g_WrL + (size_t)cta * 32 * 1280;
        #pragma unroll
        for (int i = 0; i < 40; i++) {
            int idx = tid + i * TPB;          // 0..10239
            int c   = idx >> 9;
            int rem = idx & 511;
            int half = rem >> 8;
            int row  = (rem >> 3) & 31;
            int q    = rem & 7;
            size_t so = (size_t)row * 1280 + c * 64 + q * 8;
            uint32_t d = smu + (uint32_t)(c * ACH + half * AHALF
                         + row * 128 + ((q * 16) ^ ((row & 7) << 4)));
            cp16(d, (half ? wl : wh) + so);
        }
        CP_COMMIT();
    }

    // pre-stage x chunks 0..2 for t=0
    #pragma unroll
    for (int p = 0; p < 3; p++) {
        stage_b(tid, 0, p, smu + BOFF + (uint32_t)(p * BBUF));
        CP_COMMIT();
    }

    for (int t = 0; t < Tsz; t++) {
        float acc[2][4];
        #pragma unroll
        for (int nt = 0; nt < 2; nt++)
            #pragma unroll
            for (int i = 0; i < 4; i++) acc[nt][i] = 0.0f;

        for (int c = 0; c < NCHK; c++) {
            if (c <= 17)      CP_WAIT(2);
            else if (c == 18) CP_WAIT(1);
            else              CP_WAIT(0);
            __syncthreads();
            if (c + 3 < NCHK) {
                stage_b(tid, t, c + 3, smu + BOFF + (uint32_t)(((c + 3) & 3) * BBUF));
                CP_COMMIT();
            }
            {
                const uint32_t at = smu + (uint32_t)(c * ACH);
                const uint32_t bt = smu + BOFF + (uint32_t)((c & 3) * BBUF);
                // 2-stage software pipeline over ks
                uint32_t ah[2][4], al[2][4], bh[2][4], bl[2][4];
                {
                    const uint32_t ak = (aSel) ^ aX;
                    const uint32_t bk = (bSel) ^ bX;
                    ldsm4(ah[0], at + aRB + ak);
                    ldsm4(al[0], at + AHALF + aRB + ak);
                    ldsm4(bh[0], bt + bRB + bk);
                    ldsm4(bl[0], bt + BLHALF + bRB + bk);
                }
                #pragma unroll
                for (int ks = 0; ks < 4; ks++) {
                    const int cur = ks & 1, nxt = cur ^ 1;
                    if (ks < 3) {
                        const uint32_t ak = ((uint32_t)((ks + 1) * 32) + aSel) ^ aX;
                        const uint32_t bk = ((uint32_t)((ks + 1) * 32) + bSel) ^ bX;
                        ldsm4(ah[nxt], at + aRB + ak);
                        ldsm4(al[nxt], at + AHALF + aRB + ak);
                        ldsm4(bh[nxt], bt + bRB + bk);
                        ldsm4(bl[nxt], bt + BLHALF + bRB + bk);
                    }
                    mma16816(acc[0], ah[cur], bh[cur][0], bh[cur][1]);
                    mma16816(acc[1], ah[cur], bh[cur][2], bh[cur][3]);
                    mma16816(acc[0], ah[cur], bl[cur][0], bl[cur][1]);
                    mma16816(acc[1], ah[cur], bl[cur][2], bl[cur][3]);
                    mma16816(acc[0], al[cur], bh[cur][0], bh[cur][1]);
                    mma16816(acc[1], al[cur], bh[cur][2], bh[cur][3]);
                }
            }
        }
        __syncthreads();   // all computes done before exch write (aliases B bufs)

        // ---- exchange: each warp writes its (m0 rows, n0..n0+15 cols) region ----
        #pragma unroll
        for (int nt = 0; nt < 2; nt++) {
            int col = n0 + nt * 8 + ecol;
            exch[er * EXST + col]           = acc[nt][0];
            exch[er * EXST + col + 1]       = acc[nt][1];
            exch[(er + 8) * EXST + col]     = acc[nt][2];
            exch[(er + 8) * EXST + col + 1] = acc[nt][3];
        }
        __syncthreads();

        // ---- pointwise LSTM update ----
        __nv_bfloat16* hho = g_hh[(t + 1) & 1];
        __nv_bfloat16* hlo = g_hl[(t + 1) & 1];
        float hn2[2];
        #pragma unroll
        for (int i = 0; i < 2; i++) {
            int jj = pj0 + i;
            float ig = sigmoidf_(exch[(0 * 8 + jj) * EXST + pb] + bias_pw[i][0]);
            float fg = sigmoidf_(exch[(1 * 8 + jj) * EXST + pb] + bias_pw[i][1]);
            float gg = tanhf    (exch[(2 * 8 + jj) * EXST + pb] + bias_pw[i][2]);
            float og = sigmoidf_(exch[(3 * 8 + jj) * EXST + pb] + bias_pw[i][3]);
            float cn = fg * c_reg[i] + ig * gg;
            c_reg[i] = cn;
            hn2[i] = og * tanhf(cn);
        }
        {
            int off = pb * Hsz + cta * 8 + pj0;     // even → 4B aligned
            __nv_bfloat16 h0 = __float2bfloat16(hn2[0]);
            __nv_bfloat16 h1 = __float2bfloat16(hn2[1]);
            *(__nv_bfloat162*)(hho + off) = __nv_bfloat162(h0, h1);
            *(__nv_bfloat162*)(hlo + off) = __nv_bfloat162(
                __float2bfloat16(hn2[0] - __bfloat162float(h0)),
                __float2bfloat16(hn2[1] - __bfloat162float(h1)));
            if (t == Tsz - 1) {
                g_hf[off]     = hn2[0];
                g_hf[off + 1] = hn2[1];
            }
        }

        __threadfence();
        __syncthreads();   // pointwise exch reads done -> pre-stage may clobber

        // pre-stage x chunks 0..2 for t+1 (overlaps barrier wait)
        if (t + 1 < Tsz) {
            #pragma unroll
            for (int p = 0; p < 3; p++) {
                stage_b(tid, t + 1, p, smu + BOFF + (uint32_t)(p * BBUF));
                CP_COMMIT();
            }
        }

        // ---- grid barrier ----
        if (tid == 0) {
            atomicAdd(&g_cnt, 1u);
            unsigned bound = (unsigned)(t + 1) * NCTA;
            while (*(volatile unsigned*)&g_cnt < bound) { }
            __threadfence();
        }
        __syncthreads();
    }

    // ---- final FC: CTA b < 64 computes out[b] ----
    if (cta < Bsz) {
        float s = 0.0f;
        for (int j = tid; j < Hsz; j += TPB)
            s += tanhf(g_hf[cta * Hsz + j]) * fcW[j];
        #pragma unroll
        for (int d = 16; d > 0; d >>= 1)
            s += __shfl_xor_sync(0xFFFFFFFFu, s, d);
        __shared__ float red[8];
        if (lane == 0) red[w] = s;
        __syncthreads();
        if (tid == 0) {
            float tot = 0.0f;
            #pragma unroll
            for (int i = 0; i < 8; i++) tot += red[i];
            out[cta] = tot + fcb[0];
        }
    }
}

// ---------------- fused prep kernel ----------------
#define PREP_W_BLKS 20480
#define PREP_X_BLKS 32768
#define PREP_B_BLKS 16
#define PREP_I_BLKS 256
#define PREP_GRID (PREP_W_BLKS + PREP_X_BLKS + PREP_B_BLKS + PREP_I_BLKS)

__global__ void prep_kernel(const float* __restrict__ x,
                            const float* __restrict__ Wih,
                            const float* __restrict__ Whh,
                            const float* __restrict__ bih,
                            const float* __restrict__ bhh)
{
    int bid = blockIdx.x;
    int tid = threadIdx.x;
    if (bid < PREP_W_BLKS) {
        int idx = bid * 256 + tid;
        int k  = idx % 1280;
        int rr = idx / 1280;
        int row = rr & 31, cta = rr >> 5;
        int gate = row >> 3, jj = row & 7;
        int R = gate * Hsz + cta * 8 + jj;
        float v = (k < Isz) ? Wih[(size_t)R * Isz + k]
                            : Whh[(size_t)R * Hsz + (k - Isz)];
        __nv_bfloat16 hi = __float2bfloat16(v);
        g_WrH[idx] = hi;
        g_WrL[idx] = __float2bfloat16(v - __bfloat162float(hi));
    } else if (bid < PREP_W_BLKS + PREP_X_BLKS) {
        size_t idx = (size_t)(bid - PREP_W_BLKS) * 256 + tid;
        float v = x[idx];
        __nv_bfloat16 hi = __float2bfloat16(v);
        g_xh[idx] = hi;
        g_xl[idx] = __float2bfloat16(v - __bfloat162float(hi));
    } else if (bid < PREP_W_BLKS + PREP_X_BLKS + PREP_B_BLKS) {
        int idx = (bid - PREP_W_BLKS - PREP_X_BLKS) * 256 + tid;
        int row = idx & 31, cta = idx >> 5;
        int gate = row >> 3, jj = row & 7;
        int R = gate * Hsz + cta * 8 + jj;
        g_bsum[idx] = bih[R] + bhh[R];
    } else {
        int i = (bid - PREP_W_BLKS - PREP_X_BLKS - PREP_B_BLKS) * 256 + tid;
        g_hh[0][i] = __float2bfloat16(0.0f);
        g_hl[0][i] = __float2bfloat16(0.0f);
        if (i == 0) g_cnt = 0u;
    }
}

extern "C" void kernel_launch(void* const* d_in, const int* in_sizes, int n_in,
                              void* d_out, int out_size)
{
    (void)in_sizes; (void)n_in; (void)out_size;
    const float* x   = (const float*)d_in[0];
    const float* Wih = (const float*)d_in[1];
    const float* Whh = (const float*)d_in[2];
    const float* bih = (const float*)d_in[3];
    const float* bhh = (const float*)d_in[4];
    const float* fcW = (const float*)d_in[5];
    const float* fcb = (const float*)d_in[6];
    float* out = (float*)d_out;

    cudaFuncSetAttribute(lstm_persist,
                         cudaFuncAttributeMaxDynamicSharedMemorySize, SMEM_DYN);

    prep_kernel<<<PREP_GRID, 256>>>(x, Wih, Whh, bih, bhh);
    lstm_persist<<<NCTA, TPB, SMEM_DYN>>>(fcW, fcb, out);
}

// round 11
// speedup vs baseline: 1.3944x; 1.3944x over previous
#include <cuda_runtime.h>
#include <cuda_bf16.h>
#include <cstdint>
#include <math.h>

// LSTM B=64, T=512, I=256, H=1024, O=1 — persistent mma.sync kernel.
// W resident in smem (swizzled, 160KB). K=1280 split across 4 independent
// warp-pairs (pair g owns K64 blocks k0=256b+64g, b=0..4; block0 is pure x).
// Each pair: private 16KB B buffer, named-barrier sync, per-thread cp.async.
// No block-wide syncs in the mainloop. bf16 hi/lo, 3-term MMA, fp32 accum.
// Epilogue sums the 4 pair-partials in the pointwise update.

#define NCTA 128
#define TPB  256
#define Tsz  512
#define Bsz  64
#define Isz  256
#define Hsz  1024
#define ACH   8192                      // per K64-chunk A bytes (hi 4096 + lo 4096)
#define AHALF 4096
#define ABYTES (20 * ACH)               // 163840 — W resident
#define BBUF  16384                     // per-pair B buffer (hi 8192 + lo 8192)
#define BLHALF 8192
#define BOFF  ABYTES
#define SMEM_DYN (ABYTES + 4 * BBUF)    // 229376
#define EXST 66
#define EXREG (32 * EXST)               // floats per pair partial region

// ---------------- static device scratch ----------------
__device__ __align__(16) __nv_bfloat16 g_WrH[NCTA * 32 * 1280];
__device__ __align__(16) __nv_bfloat16 g_WrL[NCTA * 32 * 1280];
__device__ __align__(16) __nv_bfloat16 g_xh[(size_t)Bsz * Tsz * Isz];
__device__ __align__(16) __nv_bfloat16 g_xl[(size_t)Bsz * Tsz * Isz];
__device__ __align__(16) __nv_bfloat16 g_hh[2][Bsz * Hsz];
__device__ __align__(16) __nv_bfloat16 g_hl[2][Bsz * Hsz];
__device__ float    g_hf[Bsz * Hsz];
__device__ float    g_bsum[NCTA * 32];
__device__ unsigned g_cnt;

// ---------------- PTX helpers ----------------
__device__ __forceinline__ uint32_t smem_u32(const void* p) {
    uint32_t a;
    asm("{ .reg .u64 t; cvta.to.shared.u64 t, %1; cvt.u32.u64 %0, t; }" : "=r"(a) : "l"(p));
    return a;
}
__device__ __forceinline__ void cp16(uint32_t dst, const void* src) {
    asm volatile("cp.async.cg.shared.global [%0], [%1], 16;" :: "r"(dst), "l"(src));
}
#define CP_COMMIT() asm volatile("cp.async.commit_group;")
#define CP_WAIT0()  asm volatile("cp.async.wait_group 0;" ::: "memory")
#define PAIR_BAR(id) asm volatile("bar.sync %0, 64;" :: "r"(id) : "memory")

__device__ __forceinline__ void ldsm4(uint32_t* r, uint32_t a) {
    asm volatile("ldmatrix.sync.aligned.m8n8.x4.shared.b16 {%0,%1,%2,%3}, [%4];"
                 : "=r"(r[0]), "=r"(r[1]), "=r"(r[2]), "=r"(r[3]) : "r"(a));
}
__device__ __forceinline__ void mma16816(float* c, const uint32_t* a,
                                         uint32_t b0, uint32_t b1) {
    asm volatile(
        "mma.sync.aligned.m16n8k16.row.col.f32.bf16.bf16.f32 "
        "{%0,%1,%2,%3}, {%4,%5,%6,%7}, {%8,%9}, {%0,%1,%2,%3};"
        : "+f"(c[0]), "+f"(c[1]), "+f"(c[2]), "+f"(c[3])
        : "r"(a[0]), "r"(a[1]), "r"(a[2]), "r"(a[3]), "r"(b0), "r"(b1));
}

__device__ __forceinline__ float sigmoidf_(float v) { return 1.0f / (1.0f + expf(-v)); }

// ---------------- persistent LSTM kernel (final FC folded in) ----------------
__global__ void __launch_bounds__(TPB, 1)
lstm_persist(const float* __restrict__ fcW, const float* __restrict__ fcb,
             float* __restrict__ out)
{
    extern __shared__ __align__(16) char sm[];
    const uint32_t smu = smem_u32(sm);
    float* exch = (float*)(sm + BOFF);       // aliases B buffers (sync-ordered)

    const int tid = threadIdx.x;
    const int cta = blockIdx.x;
    const int w = tid >> 5, lane = tid & 31;
    const int pg = w >> 1;                   // pair id 0..3
    const int ptid = tid & 63;               // thread within pair
    const int barid = pg + 1;                // named barrier id
    const int n0 = (w & 1) * 32;             // warp's n-slice within pair

    const uint32_t mybuf = smu + BOFF + (uint32_t)(pg * BBUF);

    // ldsm lane constants (128B-row swizzle: addr = row*128 + ((k*2+sel)^xrow))
    const uint32_t aRB  = (uint32_t)((lane & 15) * 128);
    const uint32_t aX   = (uint32_t)((lane & 7) << 4);
    const uint32_t aSel = (lane & 16) ? 16u : 0u;
    const uint32_t bRB  = (uint32_t)((n0 + (lane & 7) + ((lane & 16) ? 8 : 0)) * 128);
    const uint32_t bX   = (uint32_t)((lane & 7) << 4);
    const uint32_t bSel = (lane & 8) ? 16u : 0u;

    // epilogue frag mapping
    const int erl = lane >> 2;               // row within m16 tile
    const int ecol0 = n0 + 2 * (lane & 3);

    // pointwise mapping: 2 cells (pb, pj0..pj0+1)
    const int pb = tid & 63;
    const int pj0 = (tid >> 6) * 2;
    float bias_pw[2][4];
    #pragma unroll
    for (int i = 0; i < 2; i++)
        #pragma unroll
        for (int g = 0; g < 4; g++)
            bias_pw[i][g] = g_bsum[cta * 32 + g * 8 + pj0 + i];
    float c_reg[2] = {0.0f, 0.0f};

    // ---- stage resident W once (swizzled; chunk c holds K cols 64c..64c+64) ----
    {
        const __nv_bfloat16* wh = g_WrH + (size_t)cta * 32 * 1280;
        const __nv_bfloat16* wl = g_WrL + (size_t)cta * 32 * 1280;
        #pragma unroll
        for (int i = 0; i < 40; i++) {
            int idx = tid + i * TPB;          // 0..10239
            int c   = idx >> 9;
            int rem = idx & 511;
            int half = rem >> 8;
            int row  = (rem >> 3) & 31;
            int q    = rem & 7;
            size_t so = (size_t)row * 1280 + c * 64 + q * 8;
            uint32_t d = smu + (uint32_t)(c * ACH + half * AHALF
                         + row * 128 + ((q * 16) ^ ((row & 7) << 4)));
            cp16(d, (half ? wl : wh) + so);
        }
        CP_COMMIT();
    }

    // ---- pre-stage pair's x block (block 0, K cols 64*pg) for t=0 ----
    {
        #pragma unroll
        for (int i = 0; i < 8; i++) {
            int idx = ptid + i * 64;          // 0..511
            int b = idx >> 3, q = idx & 7;
            uint32_t d = mybuf + (uint32_t)(b * 128 + ((q * 16) ^ ((b & 7) << 4)));
            size_t o = ((size_t)b * Tsz + 0) * Isz + pg * 64 + q * 8;
            cp16(d, g_xh + o);
            cp16(d + BLHALF, g_xl + o);
        }
        CP_COMMIT();
    }

    for (int t = 0; t < Tsz; t++) {
        float acc[2][4][4];
        #pragma unroll
        for (int mt = 0; mt < 2; mt++)
            #pragma unroll
            for (int nf = 0; nf < 4; nf++)
                #pragma unroll
                for (int i = 0; i < 4; i++) acc[mt][nf][i] = 0.0f;

        // ---- pair-local mainloop: 5 K64 blocks, no block-wide syncs ----
        #pragma unroll
        for (int b = 0; b < 5; b++) {
            CP_WAIT0();
            PAIR_BAR(barid);                  // staged data visible to both warps
            {
                const uint32_t at = smu + (uint32_t)((b * 4 + pg) * ACH);
                #pragma unroll
                for (int ks = 0; ks < 4; ks++) {
                    const uint32_t ak = ((uint32_t)(ks * 32) + aSel) ^ aX;
                    const uint32_t bk = ((uint32_t)(ks * 32) + bSel) ^ bX;
                    uint32_t aH[2][4], aL[2][4], bH[2][4], bL[2][4];
                    ldsm4(aH[0], at + aRB + ak);
                    ldsm4(aH[1], at + 2048 + aRB + ak);
                    ldsm4(aL[0], at + AHALF + aRB + ak);
                    ldsm4(aL[1], at + AHALF + 2048 + aRB + ak);
                    ldsm4(bH[0], mybuf + bRB + bk);
                    ldsm4(bH[1], mybuf + 2048 + bRB + bk);
                    ldsm4(bL[0], mybuf + BLHALF + bRB + bk);
                    ldsm4(bL[1], mybuf + BLHALF + 2048 + bRB + bk);
                    #pragma unroll
                    for (int mt = 0; mt < 2; mt++) {
                        mma16816(acc[mt][0], aH[mt], bH[0][0], bH[0][1]);
                        mma16816(acc[mt][1], aH[mt], bH[0][2], bH[0][3]);
                        mma16816(acc[mt][2], aH[mt], bH[1][0], bH[1][1]);
                        mma16816(acc[mt][3], aH[mt], bH[1][2], bH[1][3]);
                        mma16816(acc[mt][0], aH[mt], bL[0][0], bL[0][1]);
                        mma16816(acc[mt][1], aH[mt], bL[0][2], bL[0][3]);
                        mma16816(acc[mt][2], aH[mt], bL[1][0], bL[1][1]);
                        mma16816(acc[mt][3], aH[mt], bL[1][2], bL[1][3]);
                        mma16816(acc[mt][0], aL[mt], bH[0][0], bH[0][1]);
                        mma16816(acc[mt][1], aL[mt], bH[0][2], bH[0][3]);
                        mma16816(acc[mt][2], aL[mt], bH[1][0], bH[1][1]);
                        mma16816(acc[mt][3], aL[mt], bH[1][2], bH[1][3]);
                    }
                }
            }
            PAIR_BAR(barid);                  // both warps done reading buffer
            if (b < 4) {
                // stage block b+1 (h region): h cols 256*b + 64*pg
                const int hbase = 256 * b + 64 * pg;
                const __nv_bfloat16* hh = g_hh[t & 1];
                const __nv_bfloat16* hl = g_hl[t & 1];
                #pragma unroll
                for (int i = 0; i < 8; i++) {
                    int idx = ptid + i * 64;
                    int bb = idx >> 3, q = idx & 7;
                    uint32_t d = mybuf + (uint32_t)(bb * 128 + ((q * 16) ^ ((bb & 7) << 4)));
                    size_t o = (size_t)bb * Hsz + hbase + q * 8;
                    cp16(d, hh + o);
                    cp16(d + BLHALF, hl + o);
                }
                CP_COMMIT();
            }
        }
        __syncthreads();   // all pairs done; B buffers reusable as exch

        // ---- exchange: pair pg writes its partial to region pg ----
        {
            float* ex = exch + pg * EXREG;
            #pragma unroll
            for (int mt = 0; mt < 2; mt++) {
                int r0 = mt * 16 + erl;
                #pragma unroll
                for (int nf = 0; nf < 4; nf++) {
                    int col = ecol0 + nf * 8;
                    ex[r0 * EXST + col]           = acc[mt][nf][0];
                    ex[r0 * EXST + col + 1]       = acc[mt][nf][1];
                    ex[(r0 + 8) * EXST + col]     = acc[mt][nf][2];
                    ex[(r0 + 8) * EXST + col + 1] = acc[mt][nf][3];
                }
            }
        }
        __syncthreads();

        // ---- pointwise LSTM update (sum 4 pair-partials) ----
        __nv_bfloat16* hho = g_hh[(t + 1) & 1];
        __nv_bfloat16* hlo = g_hl[(t + 1) & 1];
        float hn2[2];
        #pragma unroll
        for (int i = 0; i < 2; i++) {
            int jj = pj0 + i;
            float gv[4];
            #pragma unroll
            for (int g = 0; g < 4; g++) {
                int ro = (g * 8 + jj) * EXST + pb;
                gv[g] = (exch[ro] + exch[EXREG + ro])
                      + (exch[2 * EXREG + ro] + exch[3 * EXREG + ro])
                      + bias_pw[i][g];
            }
            float ig = sigmoidf_(gv[0]);
            float fg = sigmoidf_(gv[1]);
            float gg = tanhf(gv[2]);
            float og = sigmoidf_(gv[3]);
            float cn = fg * c_reg[i] + ig * gg;
            c_reg[i] = cn;
            hn2[i] = og * tanhf(cn);
        }
        {
            int off = pb * Hsz + cta * 8 + pj0;     // even → 4B aligned
            __nv_bfloat16 h0 = __float2bfloat16(hn2[0]);
            __nv_bfloat16 h1 = __float2bfloat16(hn2[1]);
            *(__nv_bfloat162*)(hho + off) = __nv_bfloat162(h0, h1);
            *(__nv_bfloat162*)(hlo + off) = __nv_bfloat162(
                __float2bfloat16(hn2[0] - __bfloat162float(h0)),
                __float2bfloat16(hn2[1] - __bfloat162float(h1)));
            if (t == Tsz - 1) {
                g_hf[off]     = hn2[0];
                g_hf[off + 1] = hn2[1];
            }
        }

        __threadfence();
        __syncthreads();   // exch reads done; h globally visible

        // arrive EARLY, then pre-stage next x block while others arrive
        if (tid == 0) atomicAdd(&g_cnt, 1u);
        if (t + 1 < Tsz) {
            #pragma unroll
            for (int i = 0; i < 8; i++) {
                int idx = ptid + i * 64;
                int b = idx >> 3, q = idx & 7;
                uint32_t d = mybuf + (uint32_t)(b * 128 + ((q * 16) ^ ((b & 7) << 4)));
                size_t o = ((size_t)b * Tsz + (t + 1)) * Isz + pg * 64 + q * 8;
                cp16(d, g_xh + o);
                cp16(d + BLHALF, g_xl + o);
            }
            CP_COMMIT();
        }
        if (tid == 0) {
            unsigned bound = (unsigned)(t + 1) * NCTA;
            while (*(volatile unsigned*)&g_cnt < bound) { }
            __threadfence();
        }
        __syncthreads();
    }

    // ---- final FC: CTA b < 64 computes out[b] ----
    if (cta < Bsz) {
        float s = 0.0f;
        for (int j = tid; j < Hsz; j += TPB)
            s += tanhf(g_hf[cta * Hsz + j]) * fcW[j];
        #pragma unroll
        for (int d = 16; d > 0; d >>= 1)
            s += __shfl_xor_sync(0xFFFFFFFFu, s, d);
        __shared__ float red[8];
        if (lane == 0) red[w] = s;
        __syncthreads();
        if (tid == 0) {
            float tot = 0.0f;
            #pragma unroll
            for (int i = 0; i < 8; i++) tot += red[i];
            out[cta] = tot + fcb[0];
        }
    }
}

// ---------------- fused prep kernel ----------------
#define PREP_W_BLKS 20480
#define PREP_X_BLKS 32768
#define PREP_B_BLKS 16
#define PREP_I_BLKS 256
#define PREP_GRID (PREP_W_BLKS + PREP_X_BLKS + PREP_B_BLKS + PREP_I_BLKS)

__global__ void prep_kernel(const float* __restrict__ x,
                            const float* __restrict__ Wih,
                            const float* __restrict__ Whh,
                            const float* __restrict__ bih,
                            const float* __restrict__ bhh)
{
    int bid = blockIdx.x;
    int tid = threadIdx.x;
    if (bid < PREP_W_BLKS) {
        int idx = bid * 256 + tid;
        int k  = idx % 1280;
        int rr = idx / 1280;
        int row = rr & 31, cta = rr >> 5;
        int gate = row >> 3, jj = row & 7;
        int R = gate * Hsz + cta * 8 + jj;
        float v = (k < Isz) ? Wih[(size_t)R * Isz + k]
                            : Whh[(size_t)R * Hsz + (k - Isz)];
        __nv_bfloat16 hi = __float2bfloat16(v);
        g_WrH[idx] = hi;
        g_WrL[idx] = __float2bfloat16(v - __bfloat162float(hi));
    } else if (bid < PREP_W_BLKS + PREP_X_BLKS) {
        size_t idx = (size_t)(bid - PREP_W_BLKS) * 256 + tid;
        float v = x[idx];
        __nv_bfloat16 hi = __float2bfloat16(v);
        g_xh[idx] = hi;
        g_xl[idx] = __float2bfloat16(v - __bfloat162float(hi));
    } else if (bid < PREP_W_BLKS + PREP_X_BLKS + PREP_B_BLKS) {
        int idx = (bid - PREP_W_BLKS - PREP_X_BLKS) * 256 + tid;
        int row = idx & 31, cta = idx >> 5;
        int gate = row >> 3, jj = row & 7;
        int R = gate * Hsz + cta * 8 + jj;
        g_bsum[idx] = bih[R] + bhh[R];
    } else {
        int i = (bid - PREP_W_BLKS - PREP_X_BLKS - PREP_B_BLKS) * 256 + tid;
        g_hh[0][i] = __float2bfloat16(0.0f);
        g_hl[0][i] = __float2bfloat16(0.0f);
        if (i == 0) g_cnt = 0u;
    }
}

extern "C" void kernel_launch(void* const* d_in, const int* in_sizes, int n_in,
                              void* d_out, int out_size)
{
    (void)in_sizes; (void)n_in; (void)out_size;
    const float* x   = (const float*)d_in[0];
    const float* Wih = (const float*)d_in[1];
    const float* Whh = (const float*)d_in[2];
    const float* bih = (const float*)d_in[3];
    const float* bhh = (const float*)d_in[4];
    const float* fcW = (const float*)d_in[5];
    const float* fcb = (const float*)d_in[6];
    float* out = (float*)d_out;

    cudaFuncSetAttribute(lstm_persist,
                         cudaFuncAttributeMaxDynamicSharedMemorySize, SMEM_DYN);

    prep_kernel<<<PREP_GRID, 256>>>(x, Wih, Whh, bih, bhh);
    lstm_persist<<<NCTA, TPB, SMEM_DYN>>>(fcW, fcb, out);
}

// round 12
// speedup vs baseline: 1.4137x; 1.0138x over previous
#include <cuda_runtime.h>
#include <cuda_bf16.h>
#include <cstdint>
#include <math.h>

// LSTM B=64, T=512, I=256, H=1024, O=1 — persistent mma.sync kernel.
// W resident in smem (swizzled, 160KB). K=1280 split across 4 independent
// warp-pairs; each pair owns K64 chunks c=4b+pg (b=0..4), processed as 10 K32
// sub-blocks with a per-pair DOUBLE-buffered 8KB B ring (distance-2 staging).
// Named-barrier pair sync; no block-wide syncs in the mainloop.
// bf16 hi/lo split both operands, 3-term MMA, fp32 accum.

#define NCTA 128
#define TPB  256
#define Tsz  512
#define Bsz  64
#define Isz  256
#define Hsz  1024
#define ACH   8192                      // per K64-chunk A bytes (hi 4096 + lo 4096)
#define AHALF 4096
#define ABYTES (20 * ACH)               // 163840 — W resident
#define BSUB  8192                      // per K32 sub-buffer (hi 4096 + lo 4096)
#define BL32  4096
#define BPAIR (2 * BSUB)                // 16384 per pair (double buffer)
#define BOFF  ABYTES
#define SMEM_DYN (ABYTES + 4 * BPAIR)   // 229376
#define EXST 66
#define EXREG (32 * EXST)               // floats per pair partial region

// ---------------- static device scratch ----------------
__device__ __align__(16) __nv_bfloat16 g_WrH[NCTA * 32 * 1280];
__device__ __align__(16) __nv_bfloat16 g_WrL[NCTA * 32 * 1280];
__device__ __align__(16) __nv_bfloat16 g_xh[(size_t)Bsz * Tsz * Isz];
__device__ __align__(16) __nv_bfloat16 g_xl[(size_t)Bsz * Tsz * Isz];
__device__ __align__(16) __nv_bfloat16 g_hh[2][Bsz * Hsz];
__device__ __align__(16) __nv_bfloat16 g_hl[2][Bsz * Hsz];
__device__ float    g_hf[Bsz * Hsz];
__device__ float    g_bsum[NCTA * 32];
__device__ unsigned g_cnt;

// ---------------- PTX helpers ----------------
__device__ __forceinline__ uint32_t smem_u32(const void* p) {
    uint32_t a;
    asm("{ .reg .u64 t; cvta.to.shared.u64 t, %1; cvt.u32.u64 %0, t; }" : "=r"(a) : "l"(p));
    return a;
}
__device__ __forceinline__ void cp16(uint32_t dst, const void* src) {
    asm volatile("cp.async.cg.shared.global [%0], [%1], 16;" :: "r"(dst), "l"(src));
}
#define CP_COMMIT() asm volatile("cp.async.commit_group;")
#define CP_WAIT1()  asm volatile("cp.async.wait_group 1;" ::: "memory")
#define CP_WAIT0()  asm volatile("cp.async.wait_group 0;" ::: "memory")
#define PAIR_BAR(id) asm volatile("bar.sync %0, 64;" :: "r"(id) : "memory")

__device__ __forceinline__ void ldsm4(uint32_t* r, uint32_t a) {
    asm volatile("ldmatrix.sync.aligned.m8n8.x4.shared.b16 {%0,%1,%2,%3}, [%4];"
                 : "=r"(r[0]), "=r"(r[1]), "=r"(r[2]), "=r"(r[3]) : "r"(a));
}
__device__ __forceinline__ void mma16816(float* c, const uint32_t* a,
                                         uint32_t b0, uint32_t b1) {
    asm volatile(
        "mma.sync.aligned.m16n8k16.row.col.f32.bf16.bf16.f32 "
        "{%0,%1,%2,%3}, {%4,%5,%6,%7}, {%8,%9}, {%0,%1,%2,%3};"
        : "+f"(c[0]), "+f"(c[1]), "+f"(c[2]), "+f"(c[3])
        : "r"(a[0]), "r"(a[1]), "r"(a[2]), "r"(a[3]), "r"(b0), "r"(b1));
}

__device__ __forceinline__ float sigmoidf_(float v) { return 1.0f / (1.0f + expf(-v)); }

// ---------------- stage one K32 B sub-block (64 rows x 32k, hi+lo) ----------------
// 64B rows; swizzle: quad ^= (row>>1)&3 (conflict-free for ldsm phases).
__device__ __forceinline__ void stage32(int ptid, uint32_t buf,
                                        const __nv_bfloat16* sh,
                                        const __nv_bfloat16* sl,
                                        size_t rstride) {
    #pragma unroll
    for (int i = 0; i < 4; i++) {
        int idx = ptid + i * 64;         // 0..255
        int row = idx >> 2, q = idx & 3;
        uint32_t d = buf + (uint32_t)(row * 64 + (((q ^ ((row >> 1) & 3))) << 4));
        size_t o = (size_t)row * rstride + q * 8;
        cp16(d, sh + o);
        cp16(d + BL32, sl + o);
    }
    CP_COMMIT();
}

// ---------------- persistent LSTM kernel (final FC folded in) ----------------
__global__ void __launch_bounds__(TPB, 1)
lstm_persist(const float* __restrict__ fcW, const float* __restrict__ fcb,
             float* __restrict__ out)
{
    extern __shared__ __align__(16) char sm[];
    const uint32_t smu = smem_u32(sm);
    float* exch = (float*)(sm + BOFF);       // aliases B buffers (sync-ordered)

    const int tid = threadIdx.x;
    const int cta = blockIdx.x;
    const int w = tid >> 5, lane = tid & 31;
    const int pg = w >> 1;                   // pair id 0..3
    const int ptid = tid & 63;               // thread within pair
    const int barid = pg + 1;                // named barrier id
    const int n0 = (w & 1) * 32;             // warp's n-slice within pair

    const uint32_t pbuf0 = smu + BOFF + (uint32_t)(pg * BPAIR);

    // A ldsm lane constants (128B rows, swizzle xor (row&7)<<4)
    const uint32_t aRB  = (uint32_t)((lane & 15) * 128);
    const uint32_t aX   = (uint32_t)((lane & 7) << 4);
    const uint32_t aSel = (lane & 16) ? 16u : 0u;
    // B ldsm lane constants (64B rows, swizzle xor ((row>>1)&3)<<4)
    const int bRow = n0 + (lane & 7) + ((lane & 16) ? 8 : 0);
    const uint32_t bRB  = (uint32_t)(bRow * 64);
    const uint32_t bX   = (uint32_t)(((bRow >> 1) & 3) << 4);
    const uint32_t bSel = (lane & 8) ? 16u : 0u;

    // epilogue frag mapping
    const int erl = lane >> 2;
    const int ecol0 = n0 + 2 * (lane & 3);

    // pointwise mapping: 2 cells (pb, pj0..pj0+1)
    const int pb = tid & 63;
    const int pj0 = (tid >> 6) * 2;
    float bias_pw[2][4];
    #pragma unroll
    for (int i = 0; i < 2; i++)
        #pragma unroll
        for (int g = 0; g < 4; g++)
            bias_pw[i][g] = g_bsum[cta * 32 + g * 8 + pj0 + i];
    float c_reg[2] = {0.0f, 0.0f};

    // ---- stage resident W once (swizzled; chunk c holds K cols 64c..64c+64) ----
    {
        const __nv_bfloat16* wh = g_WrH + (size_t)cta * 32 * 1280;
        const __nv_bfloat16* wl = g_WrL + (size_t)cta * 32 * 1280;
        #pragma unroll
        for (int i = 0; i < 40; i++) {
            int idx = tid + i * TPB;          // 0..10239
            int c   = idx >> 9;
            int rem = idx & 511;
            int half = rem >> 8;
            int row  = (rem >> 3) & 31;
            int q    = rem & 7;
            size_t so = (size_t)row * 1280 + c * 64 + q * 8;
            uint32_t d = smu + (uint32_t)(c * ACH + half * AHALF
                         + row * 128 + ((q * 16) ^ ((row & 7) << 4)));
            cp16(d, (half ? wl : wh) + so);
        }
        CP_COMMIT();
    }

    // ---- pre-stage both x sub-blocks (sb0, sb1) for t=0 ----
    stage32(ptid, pbuf0,        g_xh + (size_t)0 * Isz + pg * 64,
                                g_xl + (size_t)0 * Isz + pg * 64, (size_t)Tsz * Isz);
    stage32(ptid, pbuf0 + BSUB, g_xh + (size_t)0 * Isz + pg * 64 + 32,
                                g_xl + (size_t)0 * Isz + pg * 64 + 32, (size_t)Tsz * Isz);

    for (int t = 0; t < Tsz; t++) {
        float acc[2][4][4];
        #pragma unroll
        for (int mt = 0; mt < 2; mt++)
            #pragma unroll
            for (int nf = 0; nf < 4; nf++)
                #pragma unroll
                for (int i = 0; i < 4; i++) acc[mt][nf][i] = 0.0f;

        // ---- pair-local mainloop: 10 K32 sub-blocks, double-buffered ----
        #pragma unroll
        for (int sb = 0; sb < 10; sb++) {
            if (sb < 9) CP_WAIT1(); else CP_WAIT0();
            PAIR_BAR(barid);                  // sub-block sb visible to both warps
            {
                const uint32_t at = smu + (uint32_t)(((sb >> 1) * 4 + pg) * ACH);
                const uint32_t bt = pbuf0 + (uint32_t)((sb & 1) * BSUB);
                #pragma unroll
                for (int ks = 0; ks < 2; ks++) {
                    const int aks = (sb & 1) * 2 + ks;
                    const uint32_t ak = ((uint32_t)(aks * 32) + aSel) ^ aX;
                    const uint32_t bk = ((uint32_t)(ks * 32) + bSel) ^ bX;
                    uint32_t aH[2][4], aL[2][4], bH[2][4], bL[2][4];
                    ldsm4(aH[0], at + aRB + ak);
                    ldsm4(aH[1], at + 2048 + aRB + ak);
                    ldsm4(aL[0], at + AHALF + aRB + ak);
                    ldsm4(aL[1], at + AHALF + 2048 + aRB + ak);
                    ldsm4(bH[0], bt + bRB + bk);
                    ldsm4(bH[1], bt + 1024 + bRB + bk);
                    ldsm4(bL[0], bt + BL32 + bRB + bk);
                    ldsm4(bL[1], bt + BL32 + 1024 + bRB + bk);
                    #pragma unroll
                    for (int mt = 0; mt < 2; mt++) {
                        mma16816(acc[mt][0], aH[mt], bH[0][0], bH[0][1]);
                        mma16816(acc[mt][1], aH[mt], bH[0][2], bH[0][3]);
                        mma16816(acc[mt][2], aH[mt], bH[1][0], bH[1][1]);
                        mma16816(acc[mt][3], aH[mt], bH[1][2], bH[1][3]);
                        mma16816(acc[mt][0], aH[mt], bL[0][0], bL[0][1]);
                        mma16816(acc[mt][1], aH[mt], bL[0][2], bL[0][3]);
                        mma16816(acc[mt][2], aH[mt], bL[1][0], bL[1][1]);
                        mma16816(acc[mt][3], aH[mt], bL[1][2], bL[1][3]);
                        mma16816(acc[mt][0], aL[mt], bH[0][0], bH[0][1]);
                        mma16816(acc[mt][1], aL[mt], bH[0][2], bH[0][3]);
                        mma16816(acc[mt][2], aL[mt], bH[1][0], bH[1][1]);
                        mma16816(acc[mt][3], aL[mt], bH[1][2], bH[1][3]);
                    }
                }
            }
            PAIR_BAR(barid);                  // both warps done reading buffer
            if (sb + 2 < 10) {
                // stage sub-block sb+2 (always h region: chunk c'=((sb+2)>>1)*4+pg >= 4)
                const int c2 = ((sb + 2) >> 1) * 4 + pg;
                const int hk = (c2 - 4) * 64 + ((sb + 2) & 1) * 32;
                stage32(ptid, pbuf0 + (uint32_t)((sb & 1) * BSUB),
                        g_hh[t & 1] + hk, g_hl[t & 1] + hk, (size_t)Hsz);
            }
        }
        __syncthreads();   // all pairs done; B buffers reusable as exch

        // ---- exchange: pair pg writes its partial to region pg ----
        {
            float* ex = exch + pg * EXREG;
            #pragma unroll
            for (int mt = 0; mt < 2; mt++) {
                int r0 = mt * 16 + erl;
                #pragma unroll
                for (int nf = 0; nf < 4; nf++) {
                    int col = ecol0 + nf * 8;
                    ex[r0 * EXST + col]           = acc[mt][nf][0];
                    ex[r0 * EXST + col + 1]       = acc[mt][nf][1];
                    ex[(r0 + 8) * EXST + col]     = acc[mt][nf][2];
                    ex[(r0 + 8) * EXST + col + 1] = acc[mt][nf][3];
                }
            }
        }
        __syncthreads();

        // ---- pointwise LSTM update (sum 4 pair-partials) ----
        __nv_bfloat16* hho = g_hh[(t + 1) & 1];
        __nv_bfloat16* hlo = g_hl[(t + 1) & 1];
        float hn2[2];
        #pragma unroll
        for (int i = 0; i < 2; i++) {
            int jj = pj0 + i;
            float gv[4];
            #pragma unroll
            for (int g = 0; g < 4; g++) {
                int ro = (g * 8 + jj) * EXST + pb;
                gv[g] = (exch[ro] + exch[EXREG + ro])
                      + (exch[2 * EXREG + ro] + exch[3 * EXREG + ro])
                      + bias_pw[i][g];
            }
            float ig = sigmoidf_(gv[0]);
            float fg = sigmoidf_(gv[1]);
            float gg = tanhf(gv[2]);
            float og = sigmoidf_(gv[3]);
            float cn = fg * c_reg[i] + ig * gg;
            c_reg[i] = cn;
            hn2[i] = og * tanhf(cn);
        }
        {
            int off = pb * Hsz + cta * 8 + pj0;     // even → 4B aligned
            __nv_bfloat16 h0 = __float2bfloat16(hn2[0]);
            __nv_bfloat16 h1 = __float2bfloat16(hn2[1]);
            *(__nv_bfloat162*)(hho + off) = __nv_bfloat162(h0, h1);
            *(__nv_bfloat162*)(hlo + off) = __nv_bfloat162(
                __float2bfloat16(hn2[0] - __bfloat162float(h0)),
                __float2bfloat16(hn2[1] - __bfloat162float(h1)));
            if (t == Tsz - 1) {
                g_hf[off]     = hn2[0];
                g_hf[off + 1] = hn2[1];
            }
        }

        __threadfence();
        __syncthreads();   // exch reads done; h globally visible

        // arrive EARLY, then pre-stage next x sub-blocks while others arrive
        if (tid == 0) atomicAdd(&g_cnt, 1u);
        if (t + 1 < Tsz) {
            const size_t xo = (size_t)(t + 1) * Isz + pg * 64;
            stage32(ptid, pbuf0,        g_xh + xo,      g_xl + xo,      (size_t)Tsz * Isz);
            stage32(ptid, pbuf0 + BSUB, g_xh + xo + 32, g_xl + xo + 32, (size_t)Tsz * Isz);
        }
        if (tid == 0) {
            unsigned bound = (unsigned)(t + 1) * NCTA;
            while (*(volatile unsigned*)&g_cnt < bound) { }
            __threadfence();
        }
        __syncthreads();
    }

    // ---- final FC: CTA b < 64 computes out[b] ----
    if (cta < Bsz) {
        float s = 0.0f;
        for (int j = tid; j < Hsz; j += TPB)
            s += tanhf(g_hf[cta * Hsz + j]) * fcW[j];
        #pragma unroll
        for (int d = 16; d > 0; d >>= 1)
            s += __shfl_xor_sync(0xFFFFFFFFu, s, d);
        __shared__ float red[8];
        if (lane == 0) red[w] = s;
        __syncthreads();
        if (tid == 0) {
            float tot = 0.0f;
            #pragma unroll
            for (int i = 0; i < 8; i++) tot += red[i];
            out[cta] = tot + fcb[0];
        }
    }
}

// ---------------- fused prep kernel ----------------
#define PREP_W_BLKS 20480
#define PREP_X_BLKS 32768
#define PREP_B_BLKS 16
#define PREP_I_BLKS 256
#define PREP_GRID (PREP_W_BLKS + PREP_X_BLKS + PREP_B_BLKS + PREP_I_BLKS)

__global__ void prep_kernel(const float* __restrict__ x,
                            const float* __restrict__ Wih,
                            const float* __restrict__ Whh,
                            const float* __restrict__ bih,
                            const float* __restrict__ bhh)
{
    int bid = blockIdx.x;
    int tid = threadIdx.x;
    if (bid < PREP_W_BLKS) {
        int idx = bid * 256 + tid;
        int k  = idx % 1280;
        int rr = idx / 1280;
        int row = rr & 31, cta = rr >> 5;
        int gate = row >> 3, jj = row & 7;
        int R = gate * Hsz + cta * 8 + jj;
        float v = (k < Isz) ? Wih[(size_t)R * Isz + k]
                            : Whh[(size_t)R * Hsz + (k - Isz)];
        __nv_bfloat16 hi = __float2bfloat16(v);
        g_WrH[idx] = hi;
        g_WrL[idx] = __float2bfloat16(v - __bfloat162float(hi));
    } else if (bid < PREP_W_BLKS + PREP_X_BLKS) {
        size_t idx = (size_t)(bid - PREP_W_BLKS) * 256 + tid;
        float v = x[idx];
        __nv_bfloat16 hi = __float2bfloat16(v);
        g_xh[idx] = hi;
        g_xl[idx] = __float2bfloat16(v - __bfloat162float(hi));
    } else if (bid < PREP_W_BLKS + PREP_X_BLKS + PREP_B_BLKS) {
        int idx = (bid - PREP_W_BLKS - PREP_X_BLKS) * 256 + tid;
        int row = idx & 31, cta = idx >> 5;
        int gate = row >> 3, jj = row & 7;
        int R = gate * Hsz + cta * 8 + jj;
        g_bsum[idx] = bih[R] + bhh[R];
    } else {
        int i = (bid - PREP_W_BLKS - PREP_X_BLKS - PREP_B_BLKS) * 256 + tid;
        g_hh[0][i] = __float2bfloat16(0.0f);
        g_hl[0][i] = __float2bfloat16(0.0f);
        if (i == 0) g_cnt = 0u;
    }
}

extern "C" void kernel_launch(void* const* d_in, const int* in_sizes, int n_in,
                              void* d_out, int out_size)
{
    (void)in_sizes; (void)n_in; (void)out_size;
    const float* x   = (const float*)d_in[0];
    const float* Wih = (const float*)d_in[1];
    const float* Whh = (const float*)d_in[2];
    const float* bih = (const float*)d_in[3];
    const float* bhh = (const float*)d_in[4];
    const float* fcW = (const float*)d_in[5];
    const float* fcb = (const float*)d_in[6];
    float* out = (float*)d_out;

    cudaFuncSetAttribute(lstm_persist,
                         cudaFuncAttributeMaxDynamicSharedMemorySize, SMEM_DYN);

    prep_kernel<<<PREP_GRID, 256>>>(x, Wih, Whh, bih, bhh);
    lstm_persist<<<NCTA, TPB, SMEM_DYN>>>(fcW, fcb, out);
}

// round 13
// speedup vs baseline: 1.5870x; 1.1226x over previous
#include <cuda_runtime.h>
#include <cuda_fp16.h>
#include <cstdint>
#include <math.h>

// LSTM B=64, T=512, I=256, H=1024, O=1 — persistent mma.sync kernel (fp16 2-term).
// W resident in smem as single fp16 (80KB, swizzled). act = [x;h] split fp16 hi/lo.
// gates = W @ (a_hi + a_lo): 2 MMA terms (W rounding 2^-11 -> ~1e-4 output error).
// K=1280 over 4 independent warp-pairs; K32 sub-blocks, per-pair double buffer,
// named-barrier pair sync, no block-wide syncs in the mainloop.

#define NCTA 128
#define TPB  256
#define Tsz  512
#define Bsz  64
#define Isz  256
#define Hsz  1024
#define ACH   4096                      // per K64-chunk A bytes (fp16 single)
#define ABYTES (20 * ACH)               // 81920 — W resident
#define BSUB  8192                      // per K32 sub-buffer (hi 4096 + lo 4096)
#define BL32  4096
#define BPAIR (2 * BSUB)                // 16384 per pair
#define BOFF  ABYTES
#define SMEM_DYN (ABYTES + 4 * BPAIR)   // 147456
#define EXST 66
#define EXREG (32 * EXST)               // floats per pair partial region

// ---------------- static device scratch ----------------
__device__ __align__(16) __half g_Wr[NCTA * 32 * 1280];
__device__ __align__(16) __half g_xh[(size_t)Bsz * Tsz * Isz];
__device__ __align__(16) __half g_xl[(size_t)Bsz * Tsz * Isz];
__device__ __align__(16) __half g_hh[2][Bsz * Hsz];
__device__ __align__(16) __half g_hl[2][Bsz * Hsz];
__device__ float    g_hf[Bsz * Hsz];
__device__ float    g_bsum[NCTA * 32];
__device__ unsigned g_cnt;

// ---------------- PTX helpers ----------------
__device__ __forceinline__ uint32_t smem_u32(const void* p) {
    uint32_t a;
    asm("{ .reg .u64 t; cvta.to.shared.u64 t, %1; cvt.u32.u64 %0, t; }" : "=r"(a) : "l"(p));
    return a;
}
__device__ __forceinline__ void cp16(uint32_t dst, const void* src) {
    asm volatile("cp.async.cg.shared.global [%0], [%1], 16;" :: "r"(dst), "l"(src));
}
#define CP_COMMIT() asm volatile("cp.async.commit_group;")
#define CP_WAIT1()  asm volatile("cp.async.wait_group 1;" ::: "memory")
#define CP_WAIT0()  asm volatile("cp.async.wait_group 0;" ::: "memory")
#define PAIR_BAR(id) asm volatile("bar.sync %0, 64;" :: "r"(id) : "memory")

__device__ __forceinline__ void ldsm4(uint32_t* r, uint32_t a) {
    asm volatile("ldmatrix.sync.aligned.m8n8.x4.shared.b16 {%0,%1,%2,%3}, [%4];"
                 : "=r"(r[0]), "=r"(r[1]), "=r"(r[2]), "=r"(r[3]) : "r"(a));
}
__device__ __forceinline__ void mma16816(float* c, const uint32_t* a,
                                         uint32_t b0, uint32_t b1) {
    asm volatile(
        "mma.sync.aligned.m16n8k16.row.col.f32.f16.f16.f32 "
        "{%0,%1,%2,%3}, {%4,%5,%6,%7}, {%8,%9}, {%0,%1,%2,%3};"
        : "+f"(c[0]), "+f"(c[1]), "+f"(c[2]), "+f"(c[3])
        : "r"(a[0]), "r"(a[1]), "r"(a[2]), "r"(a[3]), "r"(b0), "r"(b1));
}

__device__ __forceinline__ float sigmoidf_(float v) { return 1.0f / (1.0f + expf(-v)); }

// ---------------- stage one K32 B sub-block (64 rows x 32k, hi+lo) ----------------
// 64B rows; swizzle: quad ^= (row>>1)&3 (conflict-free for ldsm phases).
__device__ __forceinline__ void stage32(int ptid, uint32_t buf,
                                        const __half* sh, const __half* sl,
                                        size_t rstride) {
    #pragma unroll
    for (int i = 0; i < 4; i++) {
        int idx = ptid + i * 64;         // 0..255
        int row = idx >> 2, q = idx & 3;
        uint32_t d = buf + (uint32_t)(row * 64 + (((q ^ ((row >> 1) & 3))) << 4));
        size_t o = (size_t)row * rstride + q * 8;
        cp16(d, sh + o);
        cp16(d + BL32, sl + o);
    }
    CP_COMMIT();
}

// ---------------- persistent LSTM kernel (final FC folded in) ----------------
__global__ void __launch_bounds__(TPB, 1)
lstm_persist(const float* __restrict__ fcW, const float* __restrict__ fcb,
             float* __restrict__ out)
{
    extern __shared__ __align__(16) char sm[];
    const uint32_t smu = smem_u32(sm);
    float* exch = (float*)(sm + BOFF);       // aliases B buffers (sync-ordered)

    const int tid = threadIdx.x;
    const int cta = blockIdx.x;
    const int w = tid >> 5, lane = tid & 31;
    const int pg = w >> 1;                   // pair id 0..3
    const int ptid = tid & 63;               // thread within pair
    const int barid = pg + 1;                // named barrier id
    const int n0 = (w & 1) * 32;             // warp's n-slice within pair

    const uint32_t pbuf0 = smu + BOFF + (uint32_t)(pg * BPAIR);

    // A ldsm lane constants (128B rows, swizzle xor (row&7)<<4)
    const uint32_t aRB  = (uint32_t)((lane & 15) * 128);
    const uint32_t aX   = (uint32_t)((lane & 7) << 4);
    const uint32_t aSel = (lane & 16) ? 16u : 0u;
    // B ldsm lane constants (64B rows, swizzle xor ((row>>1)&3)<<4)
    const int bRow = n0 + (lane & 7) + ((lane & 16) ? 8 : 0);
    const uint32_t bRB  = (uint32_t)(bRow * 64);
    const uint32_t bX   = (uint32_t)(((bRow >> 1) & 3) << 4);
    const uint32_t bSel = (lane & 8) ? 16u : 0u;

    // epilogue frag mapping
    const int erl = lane >> 2;
    const int ecol0 = n0 + 2 * (lane & 3);

    // pointwise mapping: 2 cells (pb, pj0..pj0+1)
    const int pb = tid & 63;
    const int pj0 = (tid >> 6) * 2;
    float bias_pw[2][4];
    #pragma unroll
    for (int i = 0; i < 2; i++)
        #pragma unroll
        for (int g = 0; g < 4; g++)
            bias_pw[i][g] = g_bsum[cta * 32 + g * 8 + pj0 + i];
    float c_reg[2] = {0.0f, 0.0f};

    // ---- stage resident W once (swizzled; chunk c holds K cols 64c..64c+64) ----
    {
        const __half* wp = g_Wr + (size_t)cta * 32 * 1280;
        #pragma unroll
        for (int i = 0; i < 20; i++) {
            int idx = tid + i * TPB;          // 0..5119
            int c   = idx >> 8;               // chunk 0..19
            int rem = idx & 255;
            int row = rem >> 3, q = rem & 7;
            size_t so = (size_t)row * 1280 + c * 64 + q * 8;
            uint32_t d = smu + (uint32_t)(c * ACH
                         + row * 128 + ((q * 16) ^ ((row & 7) << 4)));
            cp16(d, wp + so);
        }
        CP_COMMIT();
    }

    // ---- pre-stage both x sub-blocks (sb0, sb1) for t=0 ----
    stage32(ptid, pbuf0,        g_xh + pg * 64,      g_xl + pg * 64,      (size_t)Tsz * Isz);
    stage32(ptid, pbuf0 + BSUB, g_xh + pg * 64 + 32, g_xl + pg * 64 + 32, (size_t)Tsz * Isz);

    for (int t = 0; t < Tsz; t++) {
        float acc[2][4][4];
        #pragma unroll
        for (int mt = 0; mt < 2; mt++)
            #pragma unroll
            for (int nf = 0; nf < 4; nf++)
                #pragma unroll
                for (int i = 0; i < 4; i++) acc[mt][nf][i] = 0.0f;

        // ---- pair-local mainloop: 10 K32 sub-blocks, double-buffered ----
        #pragma unroll
        for (int sb = 0; sb < 10; sb++) {
            if (sb < 9) CP_WAIT1(); else CP_WAIT0();
            PAIR_BAR(barid);                  // sub-block sb visible to both warps
            {
                const uint32_t at = smu + (uint32_t)(((sb >> 1) * 4 + pg) * ACH);
                const uint32_t bt = pbuf0 + (uint32_t)((sb & 1) * BSUB);
                #pragma unroll
                for (int ks = 0; ks < 2; ks++) {
                    const int aks = (sb & 1) * 2 + ks;
                    const uint32_t ak = ((uint32_t)(aks * 32) + aSel) ^ aX;
                    const uint32_t bk = ((uint32_t)(ks * 32) + bSel) ^ bX;
                    uint32_t aF[2][4], bH[2][4], bL[2][4];
                    ldsm4(aF[0], at + aRB + ak);
                    ldsm4(aF[1], at + 2048 + aRB + ak);
                    ldsm4(bH[0], bt + bRB + bk);
                    ldsm4(bH[1], bt + 1024 + bRB + bk);
                    ldsm4(bL[0], bt + BL32 + bRB + bk);
                    ldsm4(bL[1], bt + BL32 + 1024 + bRB + bk);
                    #pragma unroll
                    for (int mt = 0; mt < 2; mt++) {
                        mma16816(acc[mt][0], aF[mt], bH[0][0], bH[0][1]);
                        mma16816(acc[mt][1], aF[mt], bH[0][2], bH[0][3]);
                        mma16816(acc[mt][2], aF[mt], bH[1][0], bH[1][1]);
                        mma16816(acc[mt][3], aF[mt], bH[1][2], bH[1][3]);
                        mma16816(acc[mt][0], aF[mt], bL[0][0], bL[0][1]);
                        mma16816(acc[mt][1], aF[mt], bL[0][2], bL[0][3]);
                        mma16816(acc[mt][2], aF[mt], bL[1][0], bL[1][1]);
                        mma16816(acc[mt][3], aF[mt], bL[1][2], bL[1][3]);
                    }
                }
            }
            PAIR_BAR(barid);                  // both warps done reading buffer
            if (sb + 2 < 10) {
                // stage sub-block sb+2 (always h region: chunk c'=((sb+2)>>1)*4+pg >= 4)
                const int c2 = ((sb + 2) >> 1) * 4 + pg;
                const int hk = (c2 - 4) * 64 + ((sb + 2) & 1) * 32;
                stage32(ptid, pbuf0 + (uint32_t)((sb & 1) * BSUB),
                        g_hh[t & 1] + hk, g_hl[t & 1] + hk, (size_t)Hsz);
            }
        }
        __syncthreads();   // all pairs done; B buffers reusable as exch

        // ---- exchange: pair pg writes its partial to region pg ----
        {
            float* ex = exch + pg * EXREG;
            #pragma unroll
            for (int mt = 0; mt < 2; mt++) {
                int r0 = mt * 16 + erl;
                #pragma unroll
                for (int nf = 0; nf < 4; nf++) {
                    int col = ecol0 + nf * 8;
                    ex[r0 * EXST + col]           = acc[mt][nf][0];
                    ex[r0 * EXST + col + 1]       = acc[mt][nf][1];
                    ex[(r0 + 8) * EXST + col]     = acc[mt][nf][2];
                    ex[(r0 + 8) * EXST + col + 1] = acc[mt][nf][3];
                }
            }
        }
        __syncthreads();

        // ---- pointwise LSTM update (sum 4 pair-partials) ----
        __half* hho = g_hh[(t + 1) & 1];
        __half* hlo = g_hl[(t + 1) & 1];
        float hn2[2];
        #pragma unroll
        for (int i = 0; i < 2; i++) {
            int jj = pj0 + i;
            float gv[4];
            #pragma unroll
            for (int g = 0; g < 4; g++) {
                int ro = (g * 8 + jj) * EXST + pb;
                gv[g] = (exch[ro] + exch[EXREG + ro])
                      + (exch[2 * EXREG + ro] + exch[3 * EXREG + ro])
                      + bias_pw[i][g];
            }
            float ig = sigmoidf_(gv[0]);
            float fg = sigmoidf_(gv[1]);
            float gg = tanhf(gv[2]);
            float og = sigmoidf_(gv[3]);
            float cn = fg * c_reg[i] + ig * gg;
            c_reg[i] = cn;
            hn2[i] = og * tanhf(cn);
        }
        {
            int off = pb * Hsz + cta * 8 + pj0;     // even → 4B aligned
            __half h0 = __float2half(hn2[0]);
            __half h1 = __float2half(hn2[1]);
            *(__half2*)(hho + off) = __half2(h0, h1);
            *(__half2*)(hlo + off) = __half2(
                __float2half(hn2[0] - __half2float(h0)),
                __float2half(hn2[1] - __half2float(h1)));
            if (t == Tsz - 1) {
                g_hf[off]     = hn2[0];
                g_hf[off + 1] = hn2[1];
            }
        }

        __threadfence();
        __syncthreads();   // exch reads done; h globally visible

        // arrive EARLY, then pre-stage next x sub-blocks while others arrive
        if (tid == 0) atomicAdd(&g_cnt, 1u);
        if (t + 1 < Tsz) {
            const size_t xo = (size_t)(t + 1) * Isz + pg * 64;
            stage32(ptid, pbuf0,        g_xh + xo,      g_xl + xo,      (size_t)Tsz * Isz);
            stage32(ptid, pbuf0 + BSUB, g_xh + xo + 32, g_xl + xo + 32, (size_t)Tsz * Isz);
        }
        if (tid == 0) {
            unsigned bound = (unsigned)(t + 1) * NCTA;
            while (*(volatile unsigned*)&g_cnt < bound) { }
            __threadfence();
        }
        __syncthreads();
    }

    // ---- final FC: CTA b < 64 computes out[b] ----
    if (cta < Bsz) {
        float s = 0.0f;
        for (int j = tid; j < Hsz; j += TPB)
            s += tanhf(g_hf[cta * Hsz + j]) * fcW[j];
        #pragma unroll
        for (int d = 16; d > 0; d >>= 1)
            s += __shfl_xor_sync(0xFFFFFFFFu, s, d);
        __shared__ float red[8];
        if (lane == 0) red[w] = s;
        __syncthreads();
        if (tid == 0) {
            float tot = 0.0f;
            #pragma unroll
            for (int i = 0; i < 8; i++) tot += red[i];
            out[cta] = tot + fcb[0];
        }
    }
}

// ---------------- fused prep kernel ----------------
#define PREP_W_BLKS 20480
#define PREP_X_BLKS 32768
#define PREP_B_BLKS 16
#define PREP_I_BLKS 256
#define PREP_GRID (PREP_W_BLKS + PREP_X_BLKS + PREP_B_BLKS + PREP_I_BLKS)

__global__ void prep_kernel(const float* __restrict__ x,
                            const float* __restrict__ Wih,
                            const float* __restrict__ Whh,
                            const float* __restrict__ bih,
                            const float* __restrict__ bhh)
{
    int bid = blockIdx.x;
    int tid = threadIdx.x;
    if (bid < PREP_W_BLKS) {
        int idx = bid * 256 + tid;
        int k  = idx % 1280;
        int rr = idx / 1280;
        int row = rr & 31, cta = rr >> 5;
        int gate = row >> 3, jj = row & 7;
        int R = gate * Hsz + cta * 8 + jj;
        float v = (k < Isz) ? Wih[(size_t)R * Isz + k]
                            : Whh[(size_t)R * Hsz + (k - Isz)];
        g_Wr[idx] = __float2half(v);
    } else if (bid < PREP_W_BLKS + PREP_X_BLKS) {
        size_t idx = (size_t)(bid - PREP_W_BLKS) * 256 + tid;
        float v = x[idx];
        __half hi = __float2half(v);
        g_xh[idx] = hi;
        g_xl[idx] = __float2half(v - __half2float(hi));
    } else if (bid < PREP_W_BLKS + PREP_X_BLKS + PREP_B_BLKS) {
        int idx = (bid - PREP_W_BLKS - PREP_X_BLKS) * 256 + tid;
        int row = idx & 31, cta = idx >> 5;
        int gate = row >> 3, jj = row & 7;
        int R = gate * Hsz + cta * 8 + jj;
        g_bsum[idx] = bih[R] + bhh[R];
    } else {
        int i = (bid - PREP_W_BLKS - PREP_X_BLKS - PREP_B_BLKS) * 256 + tid;
        g_hh[0][i] = __float2half(0.0f);
        g_hl[0][i] = __float2half(0.0f);
        if (i == 0) g_cnt = 0u;
    }
}

extern "C" void kernel_launch(void* const* d_in, const int* in_sizes, int n_in,
                              void* d_out, int out_size)
{
    (void)in_sizes; (void)n_in; (void)out_size;
    const float* x   = (const float*)d_in[0];
    const float* Wih = (const float*)d_in[1];
    const float* Whh = (const float*)d_in[2];
    const float* bih = (const float*)d_in[3];
    const float* bhh = (const float*)d_in[4];
    const float* fcW = (const float*)d_in[5];
    const float* fcb = (const float*)d_in[6];
    float* out = (float*)d_out;

    cudaFuncSetAttribute(lstm_persist,
                         cudaFuncAttributeMaxDynamicSharedMemorySize, SMEM_DYN);

    prep_kernel<<<PREP_GRID, 256>>>(x, Wih, Whh, bih, bhh);
    lstm_persist<<<NCTA, TPB, SMEM_DYN>>>(fcW, fcb, out);
}

// round 15
// speedup vs baseline: 1.6511x; 1.0404x over previous
#include <cuda_runtime.h>
#include <cuda_fp16.h>
#include <cstdint>
#include <math.h>

// LSTM B=64, T=512, I=256, H=1024, O=1 — persistent mma.sync kernel (fp16 2-term)
// with x-projection HOISTED out of the recurrence:
//   prep:  gx[t][4096 rows][64 b] = W_ih @ x_t  (parallel tensor-core GEMM, fp32)
//   loop:  gates = gx[t] + W_hh @ [h_hi + h_lo]   (K=1024 only)
// Recurrent: 128 CTAs x M=32 rows; 4 warp-pairs each own 4 K64 h-blocks,
// double-buffered B staging, named-barrier pair sync, no block syncs in mainloop.

#define NCTA 128
#define TPB  256
#define Tsz  512
#define Bsz  64
#define Isz  256
#define Hsz  1024
#define ACH   4096                      // per K64-chunk A bytes (fp16)
#define ABYTES (16 * ACH)               // 65536 — resident W_hh (16 chunks)
#define BBLK  16384                     // per K64 B block (hi 8192 + lo 8192)
#define BLHALF 8192
#define BPAIR (2 * BBLK)                // 32768 per pair (double buffer)
#define BOFF  ABYTES
#define GXOFF (ABYTES + 4 * BPAIR)      // 196608
#define SMEM_DYN (GXOFF + 8192)         // 204800
#define EXST 66
#define EXREG (32 * EXST)

// xproj prep kernel smem: W 4 chunks x 16KB + xh 4 x 8KB + xl 4 x 8KB
#define XP_W(cc)   ((cc) * 16384)
#define XP_XH(cc)  (65536 + (cc) * 8192)
#define XP_XL(cc)  (98304 + (cc) * 8192)
#define XP_SMEM    131072

// ---------------- static device scratch ----------------
__device__ __align__(16) __half g_Wr[NCTA * 32 * 1280];
__device__ __align__(16) __half g_xh[(size_t)Bsz * Tsz * Isz];
__device__ __align__(16) __half g_xl[(size_t)Bsz * Tsz * Isz];
__device__ __align__(16) __half g_hh[2][Bsz * Hsz];
__device__ __align__(16) __half g_hl[2][Bsz * Hsz];
__device__ __align__(16) float  g_gx[134217728];   // [512 t][128 cta][32 row][64 b]
__device__ float    g_hf[Bsz * Hsz];
__device__ float    g_bsum[NCTA * 32];
__device__ unsigned g_cnt;

// ---------------- PTX helpers ----------------
__device__ __forceinline__ uint32_t smem_u32(const void* p) {
    uint32_t a;
    asm("{ .reg .u64 t; cvta.to.shared.u64 t, %1; cvt.u32.u64 %0, t; }" : "=r"(a) : "l"(p));
    return a;
}
__device__ __forceinline__ void cp16(uint32_t dst, const void* src) {
    asm volatile("cp.async.cg.shared.global [%0], [%1], 16;" :: "r"(dst), "l"(src));
}
#define CP_COMMIT() asm volatile("cp.async.commit_group;")
#define CP_WAIT1()  asm volatile("cp.async.wait_group 1;" ::: "memory")
#define CP_WAIT0()  asm volatile("cp.async.wait_group 0;" ::: "memory")
#define PAIR_BAR(id) asm volatile("bar.sync %0, 64;" :: "r"(id) : "memory")

__device__ __forceinline__ void ldsm4(uint32_t* r, uint32_t a) {
    asm volatile("ldmatrix.sync.aligned.m8n8.x4.shared.b16 {%0,%1,%2,%3}, [%4];"
                 : "=r"(r[0]), "=r"(r[1]), "=r"(r[2]), "=r"(r[3]) : "r"(a));
}
__device__ __forceinline__ void mma16816(float* c, const uint32_t* a,
                                         uint32_t b0, uint32_t b1) {
    asm volatile(
        "mma.sync.aligned.m16n8k16.row.col.f32.f16.f16.f32 "
        "{%0,%1,%2,%3}, {%4,%5,%6,%7}, {%8,%9}, {%0,%1,%2,%3};"
        : "+f"(c[0]), "+f"(c[1]), "+f"(c[2]), "+f"(c[3])
        : "r"(a[0]), "r"(a[1]), "r"(a[2]), "r"(a[3]), "r"(b0), "r"(b1));
}

__device__ __forceinline__ float sigmoidf_(float v) { return 1.0f / (1.0f + expf(-v)); }

// ---------------- recurrent kernel ----------------
// stage one K64 h block (64 batch rows x 64 k, hi+lo), 128B rows, swizzled.
__device__ __forceinline__ void stage_h64(int ptid, uint32_t buf,
                                          const __half* hh, const __half* hl,
                                          int hbase) {
    #pragma unroll
    for (int i = 0; i < 8; i++) {
        int idx = ptid + i * 64;            // 0..511
        int row = idx >> 3, q = idx & 7;
        uint32_t d = buf + (uint32_t)(row * 128 + ((q * 16) ^ ((row & 7) << 4)));
        size_t o = (size_t)row * Hsz + hbase + q * 8;
        cp16(d, hh + o);
        cp16(d + BLHALF, hl + o);
    }
}

__global__ void __launch_bounds__(TPB, 1)
lstm_persist(const float* __restrict__ fcW, const float* __restrict__ fcb,
             float* __restrict__ out)
{
    extern __shared__ __align__(16) char sm[];
    const uint32_t smu = smem_u32(sm);
    float* exch = (float*)(sm + BOFF);       // aliases B buffers (sync-ordered)
    float* gxs  = (float*)(sm + GXOFF);

    const int tid = threadIdx.x;
    const int cta = blockIdx.x;
    const int w = tid >> 5, lane = tid & 31;
    const int pg = w >> 1;                   // pair id 0..3
    const int ptid = tid & 63;
    const int barid = pg + 1;
    const int n0 = (w & 1) * 32;

    const uint32_t pbuf0 = smu + BOFF + (uint32_t)(pg * BPAIR);

    // A ldsm lane constants (128B rows, swizzle xor (row&7)<<4)
    const uint32_t aRB  = (uint32_t)((lane & 15) * 128);
    const uint32_t aX   = (uint32_t)((lane & 7) << 4);
    const uint32_t aSel = (lane & 16) ? 16u : 0u;
    // B ldsm lane constants (same 128B-row swizzle)
    const int bRow = n0 + (lane & 7) + ((lane & 16) ? 8 : 0);
    const uint32_t bRB  = (uint32_t)(bRow * 128);
    const uint32_t bX   = (uint32_t)((bRow & 7) << 4);
    const uint32_t bSel = (lane & 8) ? 16u : 0u;

    // epilogue frag mapping
    const int erl = lane >> 2;
    const int ecol0 = n0 + 2 * (lane & 3);

    // pointwise mapping: 2 cells
    const int pb = tid & 63;
    const int pj0 = (tid >> 6) * 2;
    float bias_pw[2][4];
    #pragma unroll
    for (int i = 0; i < 2; i++)
        #pragma unroll
        for (int g = 0; g < 4; g++)
            bias_pw[i][g] = g_bsum[cta * 32 + g * 8 + pj0 + i];
    float c_reg[2] = {0.0f, 0.0f};

    // ---- stage resident W_hh once (16 K64 chunks; W cols 256+64c) ----
    {
        const __half* wp = g_Wr + (size_t)cta * 32 * 1280;
        #pragma unroll
        for (int i = 0; i < 16; i++) {
            int idx = tid + i * TPB;          // 0..4095
            int c   = idx >> 8;               // chunk 0..15
            int rem = idx & 255;
            int row = rem >> 3, q = rem & 7;
            size_t so = (size_t)row * 1280 + 256 + c * 64 + q * 8;
            uint32_t d = smu + (uint32_t)(c * ACH
                         + row * 128 + ((q * 16) ^ ((row & 7) << 4)));
            cp16(d, wp + so);
        }
        CP_COMMIT();
    }

    const float* gx_cta = g_gx + (size_t)cta * 2048;

    for (int t = 0; t < Tsz; t++) {
        float acc[2][4][4];
        #pragma unroll
        for (int mt = 0; mt < 2; mt++)
            #pragma unroll
            for (int nf = 0; nf < 4; nf++)
                #pragma unroll
                for (int i = 0; i < 4; i++) acc[mt][nf][i] = 0.0f;

        const __half* hh = g_hh[t & 1];
        const __half* hl = g_hl[t & 1];

        // ---- group0: B block 0 (chunk pg) + this pair's gx quarter ----
        stage_h64(ptid, pbuf0, hh, hl, pg * 64);
        {
            const float* gxrow = gx_cta + (size_t)t * 262144 + pg * 512;
            #pragma unroll
            for (int i = 0; i < 2; i++) {
                int idx = ptid + i * 64;      // 0..127
                cp16(smu + GXOFF + (uint32_t)(pg * 2048 + idx * 16), gxrow + idx * 4);
            }
        }
        CP_COMMIT();

        // ---- pair-local mainloop: 4 K64 blocks, double-buffered ----
        #pragma unroll
        for (int bb = 0; bb < 4; bb++) {
            if (bb < 3) {
                stage_h64(ptid, pbuf0 + (uint32_t)(((bb + 1) & 1) * BBLK),
                          hh, hl, (4 * (bb + 1) + pg) * 64);
                CP_COMMIT();
                CP_WAIT1();
            } else {
                CP_WAIT0();
            }
            PAIR_BAR(barid);                  // block bb visible to both warps
            {
                const uint32_t at = smu + (uint32_t)((4 * bb + pg) * ACH);
                const uint32_t bt = pbuf0 + (uint32_t)((bb & 1) * BBLK);
                #pragma unroll
                for (int ks = 0; ks < 4; ks++) {
                    const uint32_t ak = ((uint32_t)(ks * 32) + aSel) ^ aX;
                    const uint32_t bk = ((uint32_t)(ks * 32) + bSel) ^ bX;
                    uint32_t aF[2][4], bH[2][4], bL[2][4];
                    ldsm4(aF[0], at + aRB + ak);
                    ldsm4(aF[1], at + 2048 + aRB + ak);
                    ldsm4(bH[0], bt + bRB + bk);
                    ldsm4(bH[1], bt + 2048 + bRB + bk);
                    ldsm4(bL[0], bt + BLHALF + bRB + bk);
                    ldsm4(bL[1], bt + BLHALF + 2048 + bRB + bk);
                    #pragma unroll
                    for (int mt = 0; mt < 2; mt++) {
                        mma16816(acc[mt][0], aF[mt], bH[0][0], bH[0][1]);
                        mma16816(acc[mt][1], aF[mt], bH[0][2], bH[0][3]);
                        mma16816(acc[mt][2], aF[mt], bH[1][0], bH[1][1]);
                        mma16816(acc[mt][3], aF[mt], bH[1][2], bH[1][3]);
                        mma16816(acc[mt][0], aF[mt], bL[0][0], bL[0][1]);
                        mma16816(acc[mt][1], aF[mt], bL[0][2], bL[0][3]);
                        mma16816(acc[mt][2], aF[mt], bL[1][0], bL[1][1]);
                        mma16816(acc[mt][3], aF[mt], bL[1][2], bL[1][3]);
                    }
                }
            }
            PAIR_BAR(barid);                  // both warps done reading buffer
        }
        __syncthreads();   // all pairs done; B buffers reusable as exch

        // ---- exchange: pair pg writes its partial to region pg ----
        {
            float* ex = exch + pg * EXREG;
            #pragma unroll
            for (int mt = 0; mt < 2; mt++) {
                int r0 = mt * 16 + erl;
                #pragma unroll
                for (int nf = 0; nf < 4; nf++) {
                    int col = ecol0 + nf * 8;
                    ex[r0 * EXST + col]           = acc[mt][nf][0];
                    ex[r0 * EXST + col + 1]       = acc[mt][nf][1];
                    ex[(r0 + 8) * EXST + col]     = acc[mt][nf][2];
                    ex[(r0 + 8) * EXST + col + 1] = acc[mt][nf][3];
                }
            }
        }
        __syncthreads();

        // ---- pointwise LSTM update (4 pair-partials + gx + bias) ----
        __half* hho = g_hh[(t + 1) & 1];
        __half* hlo = g_hl[(t + 1) & 1];
        float hn2[2];
        #pragma unroll
        for (int i = 0; i < 2; i++) {
            int jj = pj0 + i;
            float gv[4];
            #pragma unroll
            for (int g = 0; g < 4; g++) {
                int row = g * 8 + jj;
                int ro = row * EXST + pb;
                gv[g] = (exch[ro] + exch[EXREG + ro])
                      + (exch[2 * EXREG + ro] + exch[3 * EXREG + ro])
                      + gxs[row * 64 + pb] + bias_pw[i][g];
            }
            float ig = sigmoidf_(gv[0]);
            float fg = sigmoidf_(gv[1]);
            float gg = tanhf(gv[2]);
            float og = sigmoidf_(gv[3]);
            float cn = fg * c_reg[i] + ig * gg;
            c_reg[i] = cn;
            hn2[i] = og * tanhf(cn);
        }
        {
            int off = pb * Hsz + cta * 8 + pj0;
            __half h0 = __float2half(hn2[0]);
            __half h1 = __float2half(hn2[1]);
            *(__half2*)(hho + off) = __half2(h0, h1);
            *(__half2*)(hlo + off) = __half2(
                __float2half(hn2[0] - __half2float(h0)),
                __float2half(hn2[1] - __half2float(h1)));
            if (t == Tsz - 1) {
                g_hf[off]     = hn2[0];
                g_hf[off + 1] = hn2[1];
            }
        }

        __threadfence();
        __syncthreads();

        // ---- grid barrier (early arrive) ----
        if (tid == 0) {
            atomicAdd(&g_cnt, 1u);
            unsigned bound = (unsigned)(t + 1) * NCTA;
            while (*(volatile unsigned*)&g_cnt < bound) { }
            __threadfence();
        }
        __syncthreads();
    }

    // ---- final FC: CTA b < 64 computes out[b] ----
    if (cta < Bsz) {
        float s = 0.0f;
        for (int j = tid; j < Hsz; j += TPB)
            s += tanhf(g_hf[cta * Hsz + j]) * fcW[j];
        #pragma unroll
        for (int d = 16; d > 0; d >>= 1)
            s += __shfl_xor_sync(0xFFFFFFFFu, s, d);
        __shared__ float red[8];
        if (lane == 0) red[w] = s;
        __syncthreads();
        if (tid == 0) {
            float tot = 0.0f;
            #pragma unroll
            for (int i = 0; i < 8; i++) tot += red[i];
            out[cta] = tot + fcb[0];
        }
    }
}

// ---------------- x-projection GEMM prep: gx[t] = W_ih @ x_t ----------------
// grid (32 mblocks, 512 t), 256 thr. Tile M=128 (4 wctas), N=64, K=256
// (2 halves of K128, pipelined). fp16 2-term (x hi/lo), fp32 out.
__global__ void __launch_bounds__(256, 1)
xproj_kernel()
{
    extern __shared__ __align__(16) char sm[];
    const uint32_t smu = smem_u32(sm);
    const int tid = threadIdx.x;
    const int mblock = blockIdx.x;
    const int t = blockIdx.y;
    const int w = tid >> 5, lane = tid & 31;
    const int m0w = w * 16;

    const uint32_t aSel = (lane & 16) ? 16u : 0u;
    const uint32_t bSel = (lane & 8) ? 16u : 0u;
    const int aRow = m0w + (lane & 15);
    const uint32_t aRB = (uint32_t)(aRow * 128);
    const uint32_t aX  = (uint32_t)((aRow & 7) << 4);
    uint32_t bRBp[4], bXp[4];
    #pragma unroll
    for (int ng = 0; ng < 4; ng++) {
        int br = ng * 16 + (lane & 7) + ((lane & 16) ? 8 : 0);
        bRBp[ng] = (uint32_t)(br * 128);
        bXp[ng]  = (uint32_t)((br & 7) << 4);
    }

    // stage half h: W chunks {2h,2h+1} + x hi/lo chunks {2h,2h+1}
    auto stage_half = [&](int h) {
        #pragma unroll
        for (int i = 0; i < 8; i++) {         // W: 2048 cp16
            int idx = tid + i * 256;
            int cc = 2 * h + (idx >> 10);
            int rem = idx & 1023;
            int row = rem >> 3, q = rem & 7;
            int r = mblock * 128 + row;
            const __half* src = g_Wr + (size_t)(r >> 5) * 40960 + (size_t)(r & 31) * 1280
                               + cc * 64 + q * 8;
            cp16(smu + (uint32_t)(XP_W(cc) + row * 128 + ((q * 16) ^ ((row & 7) << 4))), src);
        }
        #pragma unroll
        for (int i = 0; i < 8; i++) {         // x: 2048 cp16 (hi+lo)
            int idx = tid + i * 256;
            int cc = 2 * h + (idx >> 10);
            int rem = idx & 1023;
            int hf = rem >> 9;
            int row = (rem >> 3) & 63, q = rem & 7;
            const __half* base = hf ? g_xl : g_xh;
            const __half* src = base + ((size_t)row * Tsz + t) * Isz + cc * 64 + q * 8;
            int dstoff = (hf ? XP_XL(cc) : XP_XH(cc)) + row * 128 + ((q * 16) ^ ((row & 7) << 4));
            cp16(smu + (uint32_t)dstoff, src);
        }
        CP_COMMIT();
    };

    float acc[8][4];
    #pragma unroll
    for (int nf = 0; nf < 8; nf++)
        #pragma unroll
        for (int i = 0; i < 4; i++) acc[nf][i] = 0.0f;

    stage_half(0);
    stage_half(1);
    CP_WAIT1();
    __syncthreads();

    #pragma unroll
    for (int h = 0; h < 2; h++) {
        if (h == 1) { CP_WAIT0(); __syncthreads(); }
        #pragma unroll
        for (int ci = 0; ci < 2; ci++) {
            int cc = 2 * h + ci;
            const uint32_t Wt = smu + (uint32_t)XP_W(cc);
            const uint32_t Xh = smu + (uint32_t)XP_XH(cc);
            const uint32_t Xl = smu + (uint32_t)XP_XL(cc);
            #pragma unroll
            for (int ks = 0; ks < 4; ks++) {
                const uint32_t ak = ((uint32_t)(ks * 32) + aSel) ^ aX;
                uint32_t aF[4];
                ldsm4(aF, Wt + aRB + ak);
                #pragma unroll
                for (int ng = 0; ng < 4; ng++) {
                    const uint32_t bk = ((uint32_t)(ks * 32) + bSel) ^ bXp[ng];
                    uint32_t bh[4], bl[4];
                    ldsm4(bh, Xh + bRBp[ng] + bk);
                    ldsm4(bl, Xl + bRBp[ng] + bk);
                    mma16816(acc[2 * ng],     aF, bh[0], bh[1]);
                    mma16816(acc[2 * ng + 1], aF, bh[2], bh[3]);
                    mma16816(acc[2 * ng],     aF, bl[0], bl[1]);
                    mma16816(acc[2 * ng + 1], aF, bl[2], bl[3]);
                }
            }
        }
    }

    // write gx (fp32, float2 stores)
    {
        int r1 = mblock * 128 + m0w + (lane >> 2);
        int r2 = r1 + 8;
        #pragma unroll
        for (int nf = 0; nf < 8; nf++) {
            int col = nf * 8 + 2 * (lane & 3);
            size_t o1 = ((size_t)t * 128 + (r1 >> 5)) * 2048 + (size_t)(r1 & 31) * 64 + col;
            size_t o2 = ((size_t)t * 128 + (r2 >> 5)) * 2048 + (size_t)(r2 & 31) * 64 + col;
            *(float2*)(g_gx + o1) = make_float2(acc[nf][0], acc[nf][1]);
            *(float2*)(g_gx + o2) = make_float2(acc[nf][2], acc[nf][3]);
        }
    }
}

// ---------------- fused elementwise prep kernel ----------------
#define PREP_W_BLKS 20480
#define PREP_X_BLKS 32768
#define PREP_B_BLKS 16
#define PREP_I_BLKS 256
#define PREP_GRID (PREP_W_BLKS + PREP_X_BLKS + PREP_B_BLKS + PREP_I_BLKS)

__global__ void prep_kernel(const float* __restrict__ x,
                            const float* __restrict__ Wih,
                            const float* __restrict__ Whh,
                            const float* __restrict__ bih,
                            const float* __restrict__ bhh)
{
    int bid = blockIdx.x;
    int tid = threadIdx.x;
    if (bid < PREP_W_BLKS) {
        int idx = bid * 256 + tid;
        int k  = idx % 1280;
        int rr = idx / 1280;
        int row = rr & 31, cta = rr >> 5;
        int gate = row >> 3, jj = row & 7;
        int R = gate * Hsz + cta * 8 + jj;
        float v = (k < Isz) ? Wih[(size_t)R * Isz + k]
                            : Whh[(size_t)R * Hsz + (k - Isz)];
        g_Wr[idx] = __float2half(v);
    } else if (bid < PREP_W_BLKS + PREP_X_BLKS) {
        size_t idx = (size_t)(bid - PREP_W_BLKS) * 256 + tid;
        float v = x[idx];
        __half hi = __float2half(v);
        g_xh[idx] = hi;
        g_xl[idx] = __float2half(v - __half2float(hi));
    } else if (bid < PREP_W_BLKS + PREP_X_BLKS + PREP_B_BLKS) {
        int idx = (bid - PREP_W_BLKS - PREP_X_BLKS) * 256 + tid;
        int row = idx & 31, cta = idx >> 5;
        int gate = row >> 3, jj = row & 7;
        int R = gate * Hsz + cta * 8 + jj;
        g_bsum[idx] = bih[R] + bhh[R];
    } else {
        int i = (bid - PREP_W_BLKS - PREP_X_BLKS - PREP_B_BLKS) * 256 + tid;
        g_hh[0][i] = __float2half(0.0f);
        g_hl[0][i] = __float2half(0.0f);
        if (i == 0) g_cnt = 0u;
    }
}

extern "C" void kernel_launch(void* const* d_in, const int* in_sizes, int n_in,
                              void* d_out, int out_size)
{
    (void)in_sizes; (void)n_in; (void)out_size;
    const float* x   = (const float*)d_in[0];
    const float* Wih = (const float*)d_in[1];
    const float* Whh = (const float*)d_in[2];
    const float* bih = (const float*)d_in[3];
    const float* bhh = (const float*)d_in[4];
    const float* fcW = (const float*)d_in[5];
    const float* fcb = (const float*)d_in[6];
    float* out = (float*)d_out;

    cudaFuncSetAttribute(lstm_persist,
                         cudaFuncAttributeMaxDynamicSharedMemorySize, SMEM_DYN);
    cudaFuncSetAttribute(xproj_kernel,
                         cudaFuncAttributeMaxDynamicSharedMemorySize, XP_SMEM);

    prep_kernel<<<PREP_GRID, 256>>>(x, Wih, Whh, bih, bhh);
    xproj_kernel<<<dim3(32, Tsz), 256, XP_SMEM>>>();
    lstm_persist<<<NCTA, TPB, SMEM_DYN>>>(fcW, fcb, out);
}

// round 17
// speedup vs baseline: 1.6838x; 1.0198x over previous
#include <cuda_runtime.h>
#include <cuda_fp16.h>
#include <cstdint>
#include <math.h>

// LSTM B=64, T=512, I=256, H=1024, O=1 — persistent mma.sync kernel (fp16 2-term),
// x-projection hoisted (gx = W_ih @ x_t precomputed), recurrent K=1024.
// R16: proven global-barrier base + fast transcendentals + gx(t+1) staging
// overlapped with the barrier spin (own cp.async commit group).
// 128 CTAs x M=32 rows; 4 warp-pairs x 4 K64 h-blocks, double-buffered staging.

#define NCTA 128
#define TPB  256
#define Tsz  512
#define Bsz  64
#define Isz  256
#define Hsz  1024
#define ACH   4096                      // per K64-chunk A bytes (fp16)
#define ABYTES (16 * ACH)               // 65536 — resident W_hh
#define BBLK  16384                     // per K64 B block (hi 8192 + lo 8192)
#define BLHALF 8192
#define BPAIR (2 * BBLK)
#define BOFF  ABYTES
#define GXOFF (ABYTES + 4 * BPAIR)      // 196608
#define SMEM_DYN (GXOFF + 8192)         // 204800
#define EXST 66
#define EXREG (32 * EXST)

// xproj prep kernel smem layout
#define XP_W(cc)   ((cc) * 16384)
#define XP_XH(cc)  (65536 + (cc) * 8192)
#define XP_XL(cc)  (98304 + (cc) * 8192)
#define XP_SMEM    131072

// ---------------- static device scratch ----------------
__device__ __align__(16) __half g_Wr[NCTA * 32 * 1280];
__device__ __align__(16) __half g_xh[(size_t)Bsz * Tsz * Isz];
__device__ __align__(16) __half g_xl[(size_t)Bsz * Tsz * Isz];
__device__ __align__(16) __half g_hh[2][Bsz * Hsz];
__device__ __align__(16) __half g_hl[2][Bsz * Hsz];
__device__ __align__(16) float  g_gx[134217728];   // [512 t][128 cta][32 row][64 b]
__device__ float    g_hf[Bsz * Hsz];
__device__ float    g_bsum[NCTA * 32];
__device__ unsigned g_cnt;

// ---------------- PTX helpers ----------------
__device__ __forceinline__ uint32_t smem_u32(const void* p) {
    uint32_t a;
    asm("{ .reg .u64 t; cvta.to.shared.u64 t, %1; cvt.u32.u64 %0, t; }" : "=r"(a) : "l"(p));
    return a;
}
__device__ __forceinline__ void cp16(uint32_t dst, const void* src) {
    asm volatile("cp.async.cg.shared.global [%0], [%1], 16;" :: "r"(dst), "l"(src));
}
#define CP_COMMIT() asm volatile("cp.async.commit_group;")
#define CP_WAIT1()  asm volatile("cp.async.wait_group 1;" ::: "memory")
#define CP_WAIT0()  asm volatile("cp.async.wait_group 0;" ::: "memory")
#define PAIR_BAR(id) asm volatile("bar.sync %0, 64;" :: "r"(id) : "memory")

__device__ __forceinline__ void ldsm4(uint32_t* r, uint32_t a) {
    asm volatile("ldmatrix.sync.aligned.m8n8.x4.shared.b16 {%0,%1,%2,%3}, [%4];"
                 : "=r"(r[0]), "=r"(r[1]), "=r"(r[2]), "=r"(r[3]) : "r"(a));
}
__device__ __forceinline__ void mma16816(float* c, const uint32_t* a,
                                         uint32_t b0, uint32_t b1) {
    asm volatile(
        "mma.sync.aligned.m16n8k16.row.col.f32.f16.f16.f32 "
        "{%0,%1,%2,%3}, {%4,%5,%6,%7}, {%8,%9}, {%0,%1,%2,%3};"
        : "+f"(c[0]), "+f"(c[1]), "+f"(c[2]), "+f"(c[3])
        : "r"(a[0]), "r"(a[1]), "r"(a[2]), "r"(a[3]), "r"(b0), "r"(b1));
}

// saturation-safe fast transcendentals (error ~1e-6, << 1.7e-4 budget)
__device__ __forceinline__ float fast_sig(float v) {
    return __fdividef(1.0f, 1.0f + __expf(-v));
}
__device__ __forceinline__ float fast_tanh(float v) {
    float e = __expf(2.0f * v);                  // inf-safe: 1 - 2/(inf+1) = 1
    return 1.0f - __fdividef(2.0f, e + 1.0f);
}

// stage one K64 h block (64 batch rows x 64 k, hi+lo), 128B rows, swizzled.
__device__ __forceinline__ void stage_h64(int ptid, uint32_t buf,
                                          const __half* hh, const __half* hl,
                                          int hbase) {
    #pragma unroll
    for (int i = 0; i < 8; i++) {
        int idx = ptid + i * 64;            // 0..511
        int row = idx >> 3, q = idx & 7;
        uint32_t d = buf + (uint32_t)(row * 128 + ((q * 16) ^ ((row & 7) << 4)));
        size_t o = (size_t)row * Hsz + hbase + q * 8;
        cp16(d, hh + o);
        cp16(d + BLHALF, hl + o);
    }
}

__global__ void __launch_bounds__(TPB, 1)
lstm_persist(const float* __restrict__ fcW, const float* __restrict__ fcb,
             float* __restrict__ out)
{
    extern __shared__ __align__(16) char sm[];
    const uint32_t smu = smem_u32(sm);
    float* exch = (float*)(sm + BOFF);       // aliases B buffers (sync-ordered)
    float* gxs  = (float*)(sm + GXOFF);

    const int tid = threadIdx.x;
    const int cta = blockIdx.x;
    const int w = tid >> 5, lane = tid & 31;
    const int pg = w >> 1;
    const int ptid = tid & 63;
    const int barid = pg + 1;
    const int n0 = (w & 1) * 32;

    const uint32_t pbuf0 = smu + BOFF + (uint32_t)(pg * BPAIR);

    // A ldsm lane constants
    const uint32_t aRB  = (uint32_t)((lane & 15) * 128);
    const uint32_t aX   = (uint32_t)((lane & 7) << 4);
    const uint32_t aSel = (lane & 16) ? 16u : 0u;
    // B ldsm lane constants
    const int bRow = n0 + (lane & 7) + ((lane & 16) ? 8 : 0);
    const uint32_t bRB  = (uint32_t)(bRow * 128);
    const uint32_t bX   = (uint32_t)((bRow & 7) << 4);
    const uint32_t bSel = (lane & 8) ? 16u : 0u;

    // epilogue frag mapping
    const int erl = lane >> 2;
    const int ecol0 = n0 + 2 * (lane & 3);

    // pointwise mapping
    const int pb = tid & 63;
    const int pj0 = (tid >> 6) * 2;
    float bias_pw[2][4];
    #pragma unroll
    for (int i = 0; i < 2; i++)
        #pragma unroll
        for (int g = 0; g < 4; g++)
            bias_pw[i][g] = g_bsum[cta * 32 + g * 8 + pj0 + i];
    float c_reg[2] = {0.0f, 0.0f};

    const float* gx_cta = g_gx + (size_t)cta * 2048;

    // stage this pair's gx quarter for step tt (own commit group)
    auto stage_gx = [&](int tt) {
        const float* gxrow = gx_cta + (size_t)tt * 262144 + pg * 512;
        #pragma unroll
        for (int i = 0; i < 2; i++) {
            int idx = ptid + i * 64;
            cp16(smu + GXOFF + (uint32_t)(pg * 2048 + idx * 16), gxrow + idx * 4);
        }
        CP_COMMIT();
    };

    // ---- prologue: resident W_hh (group) + gx for t=0 (group) ----
    {
        const __half* wp = g_Wr + (size_t)cta * 32 * 1280;
        #pragma unroll
        for (int i = 0; i < 16; i++) {
            int idx = tid + i * TPB;
            int c   = idx >> 8;
            int rem = idx & 255;
            int row = rem >> 3, q = rem & 7;
            size_t so = (size_t)row * 1280 + 256 + c * 64 + q * 8;
            uint32_t d = smu + (uint32_t)(c * ACH
                         + row * 128 + ((q * 16) ^ ((row & 7) << 4)));
            cp16(d, wp + so);
        }
        CP_COMMIT();
    }
    stage_gx(0);

    for (int t = 0; t < Tsz; t++) {
        float acc[2][4][4];
        #pragma unroll
        for (int mt = 0; mt < 2; mt++)
            #pragma unroll
            for (int nf = 0; nf < 4; nf++)
                #pragma unroll
                for (int i = 0; i < 4; i++) acc[mt][nf][i] = 0.0f;

        const __half* hh = g_hh[t & 1];
        const __half* hl = g_hl[t & 1];

        // ---- h block0 (gx already in flight from prologue / barrier window) ----
        stage_h64(ptid, pbuf0, hh, hl, pg * 64);
        CP_COMMIT();

        // ---- pair-local mainloop: 4 K64 blocks, double-buffered ----
        #pragma unroll
        for (int bb = 0; bb < 4; bb++) {
            if (bb < 3) {
                stage_h64(ptid, pbuf0 + (uint32_t)(((bb + 1) & 1) * BBLK),
                          hh, hl, (4 * (bb + 1) + pg) * 64);
                CP_COMMIT();
                CP_WAIT1();
            } else {
                CP_WAIT0();
            }
            PAIR_BAR(barid);
            {
                const uint32_t at = smu + (uint32_t)((4 * bb + pg) * ACH);
                const uint32_t bt = pbuf0 + (uint32_t)((bb & 1) * BBLK);
                #pragma unroll
                for (int ks = 0; ks < 4; ks++) {
                    const uint32_t ak = ((uint32_t)(ks * 32) + aSel) ^ aX;
                    const uint32_t bk = ((uint32_t)(ks * 32) + bSel) ^ bX;
                    uint32_t aF[2][4], bH[2][4], bL[2][4];
                    ldsm4(aF[0], at + aRB + ak);
                    ldsm4(aF[1], at + 2048 + aRB + ak);
                    ldsm4(bH[0], bt + bRB + bk);
                    ldsm4(bH[1], bt + 2048 + bRB + bk);
                    ldsm4(bL[0], bt + BLHALF + bRB + bk);
                    ldsm4(bL[1], bt + BLHALF + 2048 + bRB + bk);
                    #pragma unroll
                    for (int mt = 0; mt < 2; mt++) {
                        mma16816(acc[mt][0], aF[mt], bH[0][0], bH[0][1]);
                        mma16816(acc[mt][1], aF[mt], bH[0][2], bH[0][3]);
                        mma16816(acc[mt][2], aF[mt], bH[1][0], bH[1][1]);
                        mma16816(acc[mt][3], aF[mt], bH[1][2], bH[1][3]);
                        mma16816(acc[mt][0], aF[mt], bL[0][0], bL[0][1]);
                        mma16816(acc[mt][1], aF[mt], bL[0][2], bL[0][3]);
                        mma16816(acc[mt][2], aF[mt], bL[1][0], bL[1][1]);
                        mma16816(acc[mt][3], aF[mt], bL[1][2], bL[1][3]);
                    }
                }
            }
            PAIR_BAR(barid);
        }
        __syncthreads();   // all pairs done; B buffers reusable as exch

        // ---- exchange ----
        {
            float* ex = exch + pg * EXREG;
            #pragma unroll
            for (int mt = 0; mt < 2; mt++) {
                int r0 = mt * 16 + erl;
                #pragma unroll
                for (int nf = 0; nf < 4; nf++) {
                    int col = ecol0 + nf * 8;
                    ex[r0 * EXST + col]           = acc[mt][nf][0];
                    ex[r0 * EXST + col + 1]       = acc[mt][nf][1];
                    ex[(r0 + 8) * EXST + col]     = acc[mt][nf][2];
                    ex[(r0 + 8) * EXST + col + 1] = acc[mt][nf][3];
                }
            }
        }
        __syncthreads();

        // ---- pointwise LSTM update ----
        __half* hho = g_hh[(t + 1) & 1];
        __half* hlo = g_hl[(t + 1) & 1];
        float hn2[2];
        #pragma unroll
        for (int i = 0; i < 2; i++) {
            int jj = pj0 + i;
            float gv[4];
            #pragma unroll
            for (int g = 0; g < 4; g++) {
                int row = g * 8 + jj;
                int ro = row * EXST + pb;
                gv[g] = (exch[ro] + exch[EXREG + ro])
                      + (exch[2 * EXREG + ro] + exch[3 * EXREG + ro])
                      + gxs[row * 64 + pb] + bias_pw[i][g];
            }
            float ig = fast_sig(gv[0]);
            float fg = fast_sig(gv[1]);
            float gg = fast_tanh(gv[2]);
            float og = fast_sig(gv[3]);
            float cn = fg * c_reg[i] + ig * gg;
            c_reg[i] = cn;
            hn2[i] = og * fast_tanh(cn);
        }
        {
            int off = pb * Hsz + cta * 8 + pj0;
            __half h0 = __float2half(hn2[0]);
            __half h1 = __float2half(hn2[1]);
            *(__half2*)(hho + off) = __half2(h0, h1);
            *(__half2*)(hlo + off) = __half2(
                __float2half(hn2[0] - __half2float(h0)),
                __float2half(hn2[1] - __half2float(h1)));
            if (t == Tsz - 1) {
                g_hf[off]     = hn2[0];
                g_hf[off + 1] = hn2[1];
            }
        }

        __threadfence();
        __syncthreads();   // h visible; exch + gxs reads complete

        // ---- grid barrier: arrive, stage gx(t+1) during the spin, then wait ----
        if (tid == 0) atomicAdd(&g_cnt, 1u);
        if (t + 1 < Tsz) stage_gx(t + 1);    // no h dependency; hidden by spin
        if (tid == 0) {
            unsigned bound = (unsigned)(t + 1) * NCTA;
            while (*(volatile unsigned*)&g_cnt < bound) { }
            __threadfence();
        }
        __syncthreads();
    }

    // ---- final FC: CTA b < 64 computes out[b] ----
    if (cta < Bsz) {
        float s = 0.0f;
        for (int j = tid; j < Hsz; j += TPB)
            s += fast_tanh(g_hf[cta * Hsz + j]) * fcW[j];
        #pragma unroll
        for (int d = 16; d > 0; d >>= 1)
            s += __shfl_xor_sync(0xFFFFFFFFu, s, d);
        __shared__ float red[8];
        if (lane == 0) red[w] = s;
        __syncthreads();
        if (tid == 0) {
            float tot = 0.0f;
            #pragma unroll
            for (int i = 0; i < 8; i++) tot += red[i];
            out[cta] = tot + fcb[0];
        }
    }
}

// ---------------- x-projection GEMM prep: gx[t] = W_ih @ x_t ----------------
__global__ void __launch_bounds__(256, 1)
xproj_kernel()
{
    extern __shared__ __align__(16) char sm[];
    const uint32_t smu = smem_u32(sm);
    const int tid = threadIdx.x;
    const int mblock = blockIdx.x;
    const int t = blockIdx.y;
    const int w = tid >> 5, lane = tid & 31;
    const int m0w = w * 16;

    const uint32_t aSel = (lane & 16) ? 16u : 0u;
    const uint32_t bSel = (lane & 8) ? 16u : 0u;
    const int aRow = m0w + (lane & 15);
    const uint32_t aRB = (uint32_t)(aRow * 128);
    const uint32_t aX  = (uint32_t)((aRow & 7) << 4);
    uint32_t bRBp[4], bXp[4];
    #pragma unroll
    for (int ng = 0; ng < 4; ng++) {
        int br = ng * 16 + (lane & 7) + ((lane & 16) ? 8 : 0);
        bRBp[ng] = (uint32_t)(br * 128);
        bXp[ng]  = (uint32_t)((br & 7) << 4);
    }

    auto stage_half = [&](int h) {
        #pragma unroll
        for (int i = 0; i < 8; i++) {         // W
            int idx = tid + i * 256;
            int cc = 2 * h + (idx >> 10);
            int rem = idx & 1023;
            int row = rem >> 3, q = rem & 7;
            int r = mblock * 128 + row;
            const __half* src = g_Wr + (size_t)(r >> 5) * 40960 + (size_t)(r & 31) * 1280
                               + cc * 64 + q * 8;
            cp16(smu + (uint32_t)(XP_W(cc) + row * 128 + ((q * 16) ^ ((row & 7) << 4))), src);
        }
        #pragma unroll
        for (int i = 0; i < 8; i++) {         // x hi/lo
            int idx = tid + i * 256;
            int cc = 2 * h + (idx >> 10);
            int rem = idx & 1023;
            int hf = rem >> 9;
            int row = (rem >> 3) & 63, q = rem & 7;
            const __half* base = hf ? g_xl : g_xh;
            const __half* src = base + ((size_t)row * Tsz + t) * Isz + cc * 64 + q * 8;
            int dstoff = (hf ? XP_XL(cc) : XP_XH(cc)) + row * 128 + ((q * 16) ^ ((row & 7) << 4));
            cp16(smu + (uint32_t)dstoff, src);
        }
        CP_COMMIT();
    };

    float acc[8][4];
    #pragma unroll
    for (int nf = 0; nf < 8; nf++)
        #pragma unroll
        for (int i = 0; i < 4; i++) acc[nf][i] = 0.0f;

    stage_half(0);
    stage_half(1);
    CP_WAIT1();
    __syncthreads();

    #pragma unroll
    for (int h = 0; h < 2; h++) {
        if (h == 1) { CP_WAIT0(); __syncthreads(); }
        #pragma unroll
        for (int ci = 0; ci < 2; ci++) {
            int cc = 2 * h + ci;
            const uint32_t Wt = smu + (uint32_t)XP_W(cc);
            const uint32_t Xh = smu + (uint32_t)XP_XH(cc);
            const uint32_t Xl = smu + (uint32_t)XP_XL(cc);
            #pragma unroll
            for (int ks = 0; ks < 4; ks++) {
                const uint32_t ak = ((uint32_t)(ks * 32) + aSel) ^ aX;
                uint32_t aF[4];
                ldsm4(aF, Wt + aRB + ak);
                #pragma unroll
                for (int ng = 0; ng < 4; ng++) {
                    const uint32_t bk = ((uint32_t)(ks * 32) + bSel) ^ bXp[ng];
                    uint32_t bh[4], bl[4];
                    ldsm4(bh, Xh + bRBp[ng] + bk);
                    ldsm4(bl, Xl + bRBp[ng] + bk);
                    mma16816(acc[2 * ng],     aF, bh[0], bh[1]);
                    mma16816(acc[2 * ng + 1], aF, bh[2], bh[3]);
                    mma16816(acc[2 * ng],     aF, bl[0], bl[1]);
                    mma16816(acc[2 * ng + 1], aF, bl[2], bl[3]);
                }
            }
        }
    }

    {
        int r1 = mblock * 128 + m0w + (lane >> 2);
        int r2 = r1 + 8;
        #pragma unroll
        for (int nf = 0; nf < 8; nf++) {
            int col = nf * 8 + 2 * (lane & 3);
            size_t o1 = ((size_t)t * 128 + (r1 >> 5)) * 2048 + (size_t)(r1 & 31) * 64 + col;
            size_t o2 = ((size_t)t * 128 + (r2 >> 5)) * 2048 + (size_t)(r2 & 31) * 64 + col;
            *(float2*)(g_gx + o1) = make_float2(acc[nf][0], acc[nf][1]);
            *(float2*)(g_gx + o2) = make_float2(acc[nf][2], acc[nf][3]);
        }
    }
}

// ---------------- fused elementwise prep kernel ----------------
#define PREP_W_BLKS 20480
#define PREP_X_BLKS 32768
#define PREP_B_BLKS 16
#define PREP_I_BLKS 256
#define PREP_GRID (PREP_W_BLKS + PREP_X_BLKS + PREP_B_BLKS + PREP_I_BLKS)

__global__ void prep_kernel(const float* __restrict__ x,
                            const float* __restrict__ Wih,
                            const float* __restrict__ Whh,
                            const float* __restrict__ bih,
                            const float* __restrict__ bhh)
{
    int bid = blockIdx.x;
    int tid = threadIdx.x;
    if (bid < PREP_W_BLKS) {
        int idx = bid * 256 + tid;
        int k  = idx % 1280;
        int rr = idx / 1280;
        int row = rr & 31, cta = rr >> 5;
        int gate = row >> 3, jj = row & 7;
        int R = gate * Hsz + cta * 8 + jj;
        float v = (k < Isz) ? Wih[(size_t)R * Isz + k]
                            : Whh[(size_t)R * Hsz + (k - Isz)];
        g_Wr[idx] = __float2half(v);
    } else if (bid < PREP_W_BLKS + PREP_X_BLKS) {
        size_t idx = (size_t)(bid - PREP_W_BLKS) * 256 + tid;
        float v = x[idx];
        __half hi = __float2half(v);
        g_xh[idx] = hi;
        g_xl[idx] = __float2half(v - __half2float(hi));
    } else if (bid < PREP_W_BLKS + PREP_X_BLKS + PREP_B_BLKS) {
        int idx = (bid - PREP_W_BLKS - PREP_X_BLKS) * 256 + tid;
        int row = idx & 31, cta = idx >> 5;
        int gate = row >> 3, jj = row & 7;
        int R = gate * Hsz + cta * 8 + jj;
        g_bsum[idx] = bih[R] + bhh[R];
    } else {
        int i = (bid - PREP_W_BLKS - PREP_X_BLKS - PREP_B_BLKS) * 256 + tid;
        g_hh[0][i] = __float2half(0.0f);
        g_hl[0][i] = __float2half(0.0f);
        if (i == 0) g_cnt = 0u;
    }
}

extern "C" void kernel_launch(void* const* d_in, const int* in_sizes, int n_in,
                              void* d_out, int out_size)
{
    (void)in_sizes; (void)n_in; (void)out_size;
    const float* x   = (const float*)d_in[0];
    const float* Wih = (const float*)d_in[1];
    const float* Whh = (const float*)d_in[2];
    const float* bih = (const float*)d_in[3];
    const float* bhh = (const float*)d_in[4];
    const float* fcW = (const float*)d_in[5];
    const float* fcb = (const float*)d_in[6];
    float* out = (float*)d_out;

    cudaFuncSetAttribute(lstm_persist,
                         cudaFuncAttributeMaxDynamicSharedMemorySize, SMEM_DYN);
    cudaFuncSetAttribute(xproj_kernel,
                         cudaFuncAttributeMaxDynamicSharedMemorySize, XP_SMEM);

    prep_kernel<<<PREP_GRID, 256>>>(x, Wih, Whh, bih, bhh);
    xproj_kernel<<<dim3(32, Tsz), 256, XP_SMEM>>>();
    lstm_persist<<<NCTA, TPB, SMEM_DYN>>>(fcW, fcb, out);
}